// round 1
// baseline (speedup 1.0000x reference)
#include <cuda_runtime.h>

#define NN   50000
#define EE   640000
#define DIN  128
#define DOUT 256
#define BN_EPS 1e-5f

// ---------------- scratch (static __device__, no allocation) ----------------
__device__ __align__(16) float g_agg[(size_t)NN * DIN];   // 25.6 MB
__device__ float g_cnt[NN];
__device__ float g_sum[DOUT];
__device__ float g_sqsum[DOUT];
__device__ float g_scale[DOUT];
__device__ float g_shift[DOUT];
__device__ int   g_is64;

// ---------------- dtype detection for edge_index (int64 vs int32) ----------
__global__ void k_detect(const unsigned* __restrict__ ei) {
    if (threadIdx.x == 0 && blockIdx.x == 0) {
        unsigned acc = 0;
        // if int64 (little-endian, values < 50000), every odd 32-bit word is 0
        #pragma unroll
        for (int i = 0; i < 8; i++) acc |= ei[2 * i + 1];
        acc |= ei[2 * EE - 1];
        g_is64 = (acc == 0u) ? 1 : 0;
    }
}

// ---------------- zero scratch each call ------------------------------------
__global__ void k_zero() {
    size_t i = (size_t)blockIdx.x * blockDim.x + threadIdx.x;
    size_t stride = (size_t)gridDim.x * blockDim.x;
    float4 z = make_float4(0.f, 0.f, 0.f, 0.f);
    float4* pa = (float4*)g_agg;
    for (size_t j = i; j < (size_t)NN * (DIN / 4); j += stride) pa[j] = z;
    for (size_t j = i; j < NN; j += stride) g_cnt[j] = 0.f;
    if (i < DOUT) { g_sum[i] = 0.f; g_sqsum[i] = 0.f; }
}

// ---------------- edge scatter: warp per edge, red.v4 -----------------------
__global__ __launch_bounds__(256) void k_scatter(const void* __restrict__ eiv,
                                                 const float* __restrict__ x) {
    int w = (int)((blockIdx.x * blockDim.x + threadIdx.x) >> 5);
    int lane = threadIdx.x & 31;
    if (w >= EE) return;
    int s, d;
    if (g_is64) {
        const long long* ei = (const long long*)eiv;
        s = (int)ei[w];
        d = (int)ei[EE + w];
    } else {
        const int* ei = (const int*)eiv;
        s = ei[w];
        d = ei[EE + w];
    }
    float4 v = __ldg((const float4*)x + (size_t)s * (DIN / 4) + lane);
    float* dst = g_agg + (size_t)d * DIN + lane * 4;
    asm volatile("red.global.add.v4.f32 [%0], {%1,%2,%3,%4};"
                 :: "l"(dst), "f"(v.x), "f"(v.y), "f"(v.z), "f"(v.w) : "memory");
    if (lane == 0) {
        float* c = g_cnt + d;
        asm volatile("red.global.add.f32 [%0], %1;" :: "l"(c), "f"(1.0f) : "memory");
    }
}

// ---------------- GEMM 1: pre = agg@Wl^T + x@Wr^T + b_l, + BN stats ---------
// block: 256 threads, tile 128 rows x 128 cols, 8x8 per thread, k-chunk 8
__global__ __launch_bounds__(256, 1) void k_gemm_pre(
    const float* __restrict__ x, const float* __restrict__ Wl,
    const float* __restrict__ bl, const float* __restrict__ Wr,
    float* __restrict__ pre)
{
    __shared__ float sInv[128];
    __shared__ union U {
        struct { float Ag[8][128]; float Ax[8][128]; float Bl[8][128]; float Br[8][128]; } t;
        float red[16][128];
    } u;

    const int t = threadIdx.x;
    const int row0 = blockIdx.x * 128;
    const int col0 = blockIdx.y * 128;

    if (t < 128) {
        int r = row0 + t; if (r > NN - 1) r = NN - 1;
        sInv[t] = 1.0f / fmaxf(g_cnt[r], 1.0f);
    }
    __syncthreads();

    const int lr = t >> 1;          // loader row 0..127
    const int lk = (t & 1) << 2;    // loader k offset 0 or 4
    int ar = row0 + lr; if (ar > NN - 1) ar = NN - 1;
    const float inv = sInv[lr];
    const float* pAg = g_agg + (size_t)ar * DIN;
    const float* pAx = x + (size_t)ar * DIN;
    const float* pBl = Wl + (size_t)(col0 + lr) * DIN;
    const float* pBr = Wr + (size_t)(col0 + lr) * DIN;

    float acc[8][8];
    #pragma unroll
    for (int i = 0; i < 8; i++)
        #pragma unroll
        for (int j = 0; j < 8; j++) acc[i][j] = 0.f;

    const int ty = t >> 4;   // 0..15 row group
    const int tx = t & 15;   // 0..15 col group

    for (int kc = 0; kc < DIN; kc += 8) {
        float4 ag = *(const float4*)(pAg + kc + lk);
        float4 ax = *(const float4*)(pAx + kc + lk);
        float4 wl = *(const float4*)(pBl + kc + lk);
        float4 wr = *(const float4*)(pBr + kc + lk);
        __syncthreads();
        u.t.Ag[lk + 0][lr] = ag.x * inv; u.t.Ag[lk + 1][lr] = ag.y * inv;
        u.t.Ag[lk + 2][lr] = ag.z * inv; u.t.Ag[lk + 3][lr] = ag.w * inv;
        u.t.Ax[lk + 0][lr] = ax.x; u.t.Ax[lk + 1][lr] = ax.y;
        u.t.Ax[lk + 2][lr] = ax.z; u.t.Ax[lk + 3][lr] = ax.w;
        u.t.Bl[lk + 0][lr] = wl.x; u.t.Bl[lk + 1][lr] = wl.y;
        u.t.Bl[lk + 2][lr] = wl.z; u.t.Bl[lk + 3][lr] = wl.w;
        u.t.Br[lk + 0][lr] = wr.x; u.t.Br[lk + 1][lr] = wr.y;
        u.t.Br[lk + 2][lr] = wr.z; u.t.Br[lk + 3][lr] = wr.w;
        __syncthreads();
        #pragma unroll
        for (int k = 0; k < 8; k++) {
            float4 a0 = *(const float4*)&u.t.Ag[k][ty * 4];
            float4 a1 = *(const float4*)&u.t.Ag[k][64 + ty * 4];
            float4 b0 = *(const float4*)&u.t.Ax[k][ty * 4];
            float4 b1 = *(const float4*)&u.t.Ax[k][64 + ty * 4];
            float4 w0 = *(const float4*)&u.t.Bl[k][tx * 4];
            float4 w1 = *(const float4*)&u.t.Bl[k][64 + tx * 4];
            float4 r0 = *(const float4*)&u.t.Br[k][tx * 4];
            float4 r1 = *(const float4*)&u.t.Br[k][64 + tx * 4];
            float Av[8] = {a0.x, a0.y, a0.z, a0.w, a1.x, a1.y, a1.z, a1.w};
            float Xv[8] = {b0.x, b0.y, b0.z, b0.w, b1.x, b1.y, b1.z, b1.w};
            float Wv[8] = {w0.x, w0.y, w0.z, w0.w, w1.x, w1.y, w1.z, w1.w};
            float Rv[8] = {r0.x, r0.y, r0.z, r0.w, r1.x, r1.y, r1.z, r1.w};
            #pragma unroll
            for (int i = 0; i < 8; i++)
                #pragma unroll
                for (int j = 0; j < 8; j++)
                    acc[i][j] += Av[i] * Wv[j] + Xv[i] * Rv[j];
        }
    }

    // add bias
    float bv[8];
    #pragma unroll
    for (int j = 0; j < 8; j++) {
        int cl = (j < 4) ? (tx * 4 + j) : (64 + tx * 4 + (j - 4));
        bv[j] = __ldg(&bl[col0 + cl]);
    }
    #pragma unroll
    for (int i = 0; i < 8; i++)
        #pragma unroll
        for (int j = 0; j < 8; j++) acc[i][j] += bv[j];

    // store pre + accumulate per-thread column stats
    float ps[8], pq[8];
    #pragma unroll
    for (int j = 0; j < 8; j++) { ps[j] = 0.f; pq[j] = 0.f; }
    #pragma unroll
    for (int i = 0; i < 8; i++) {
        int rl = (i < 4) ? (ty * 4 + i) : (64 + ty * 4 + (i - 4));
        int r = row0 + rl;
        if (r < NN) {
            size_t base = (size_t)r * DOUT + col0;
            *(float4*)(pre + base + tx * 4) =
                make_float4(acc[i][0], acc[i][1], acc[i][2], acc[i][3]);
            *(float4*)(pre + base + 64 + tx * 4) =
                make_float4(acc[i][4], acc[i][5], acc[i][6], acc[i][7]);
            #pragma unroll
            for (int j = 0; j < 8; j++) {
                ps[j] += acc[i][j];
                pq[j] += acc[i][j] * acc[i][j];
            }
        }
    }

    // reduce stats across block, one atomic per column
    __syncthreads();
    #pragma unroll
    for (int j = 0; j < 8; j++) {
        int cl = (j < 4) ? (tx * 4 + j) : (64 + tx * 4 + (j - 4));
        u.red[ty][cl] = ps[j];
    }
    __syncthreads();
    if (t < 128) {
        float s = 0.f;
        #pragma unroll
        for (int q = 0; q < 16; q++) s += u.red[q][t];
        atomicAdd(&g_sum[col0 + t], s);
    }
    __syncthreads();
    #pragma unroll
    for (int j = 0; j < 8; j++) {
        int cl = (j < 4) ? (tx * 4 + j) : (64 + tx * 4 + (j - 4));
        u.red[ty][cl] = pq[j];
    }
    __syncthreads();
    if (t < 128) {
        float s = 0.f;
        #pragma unroll
        for (int q = 0; q < 16; q++) s += u.red[q][t];
        atomicAdd(&g_sqsum[col0 + t], s);
    }
}

// ---------------- BN stats finalize ------------------------------------------
__global__ void k_stats(const float* __restrict__ gamma, const float* __restrict__ beta) {
    int j = threadIdx.x;
    const float invN = 1.0f / (float)NN;
    float mean = g_sum[j] * invN;
    float var = g_sqsum[j] * invN - mean * mean;
    float rstd = rsqrtf(var + BN_EPS);
    float sc = rstd * gamma[j];
    g_scale[j] = sc;
    g_shift[j] = beta[j] - mean * sc;
}

// ---------------- GEMM 2: id = x@Wres^T + b_res, fused BN/ReLU/add ----------
__global__ __launch_bounds__(256, 1) void k_gemm_final(
    const float* __restrict__ x, const float* __restrict__ Wres,
    const float* __restrict__ bres, float* __restrict__ out)
{
    __shared__ float sA[8][128];
    __shared__ float sB[8][128];
    const int t = threadIdx.x;
    const int row0 = blockIdx.x * 128;
    const int col0 = blockIdx.y * 128;
    const int lr = t >> 1;
    const int lk = (t & 1) << 2;
    int ar = row0 + lr; if (ar > NN - 1) ar = NN - 1;
    const float* pA = x + (size_t)ar * DIN;
    const float* pB = Wres + (size_t)(col0 + lr) * DIN;

    float acc[8][8];
    #pragma unroll
    for (int i = 0; i < 8; i++)
        #pragma unroll
        for (int j = 0; j < 8; j++) acc[i][j] = 0.f;

    const int ty = t >> 4;
    const int tx = t & 15;

    for (int kc = 0; kc < DIN; kc += 8) {
        float4 a = *(const float4*)(pA + kc + lk);
        float4 b = *(const float4*)(pB + kc + lk);
        __syncthreads();
        sA[lk + 0][lr] = a.x; sA[lk + 1][lr] = a.y; sA[lk + 2][lr] = a.z; sA[lk + 3][lr] = a.w;
        sB[lk + 0][lr] = b.x; sB[lk + 1][lr] = b.y; sB[lk + 2][lr] = b.z; sB[lk + 3][lr] = b.w;
        __syncthreads();
        #pragma unroll
        for (int k = 0; k < 8; k++) {
            float4 a0 = *(const float4*)&sA[k][ty * 4];
            float4 a1 = *(const float4*)&sA[k][64 + ty * 4];
            float4 w0 = *(const float4*)&sB[k][tx * 4];
            float4 w1 = *(const float4*)&sB[k][64 + tx * 4];
            float Av[8] = {a0.x, a0.y, a0.z, a0.w, a1.x, a1.y, a1.z, a1.w};
            float Wv[8] = {w0.x, w0.y, w0.z, w0.w, w1.x, w1.y, w1.z, w1.w};
            #pragma unroll
            for (int i = 0; i < 8; i++)
                #pragma unroll
                for (int j = 0; j < 8; j++)
                    acc[i][j] += Av[i] * Wv[j];
        }
    }

    float sc[8], sh[8], bv[8];
    #pragma unroll
    for (int j = 0; j < 8; j++) {
        int cl = (j < 4) ? (tx * 4 + j) : (64 + tx * 4 + (j - 4));
        int c = col0 + cl;
        sc[j] = g_scale[c];
        sh[j] = g_shift[c];
        bv[j] = __ldg(&bres[c]);
    }
    #pragma unroll
    for (int i = 0; i < 8; i++) {
        int rl = (i < 4) ? (ty * 4 + i) : (64 + ty * 4 + (i - 4));
        int r = row0 + rl;
        if (r < NN) {
            size_t base = (size_t)r * DOUT + col0;
            float4 p0 = *(const float4*)(out + base + tx * 4);
            float4 p1 = *(const float4*)(out + base + 64 + tx * 4);
            float pv[8] = {p0.x, p0.y, p0.z, p0.w, p1.x, p1.y, p1.z, p1.w};
            float o[8];
            #pragma unroll
            for (int j = 0; j < 8; j++)
                o[j] = fmaxf(pv[j] * sc[j] + sh[j], 0.f) + acc[i][j] + bv[j];
            *(float4*)(out + base + tx * 4) = make_float4(o[0], o[1], o[2], o[3]);
            *(float4*)(out + base + 64 + tx * 4) = make_float4(o[4], o[5], o[6], o[7]);
        }
    }
}

// ---------------- launch ------------------------------------------------------
extern "C" void kernel_launch(void* const* d_in, const int* in_sizes, int n_in,
                              void* d_out, int out_size) {
    const float* x     = (const float*)d_in[0];
    const void*  ei    = d_in[1];
    const float* Wl    = (const float*)d_in[2];
    const float* bl    = (const float*)d_in[3];
    const float* Wr    = (const float*)d_in[4];
    const float* Wres  = (const float*)d_in[5];
    const float* bres  = (const float*)d_in[6];
    const float* gamma = (const float*)d_in[7];
    const float* beta  = (const float*)d_in[8];
    float* out = (float*)d_out;

    k_detect<<<1, 1>>>((const unsigned*)ei);
    k_zero<<<4096, 256>>>();
    k_scatter<<<(EE + 7) / 8, 256>>>(ei, x);
    dim3 g1((NN + 127) / 128, DOUT / 128);
    k_gemm_pre<<<g1, 256>>>(x, Wl, bl, Wr, out);
    k_stats<<<1, DOUT>>>(gamma, beta);
    k_gemm_final<<<g1, 256>>>(x, Wres, bres, out);
}

// round 4
// speedup vs baseline: 1.2576x; 1.2576x over previous
#include <cuda_runtime.h>
#include <cstdint>

#define NN   50000
#define EE   640000
#define DIN  128
#define DOUT 256
#define BN_EPS 1e-5f
#define MTILE 128
#define NTILES ((NN + MTILE - 1) / MTILE)   // 391

// smem tile strides (floats): rows padded 16 -> 20 to break bank conflicts
#define SROW 20
#define A_TILE_F (128 * SROW)     // 2560 floats per 128x16 tile
#define B_TILE_F (256 * SROW)     // 5120 floats per 256x16 tile

// ---------------- scratch (static __device__, no allocation) ----------------
__device__ __align__(16) float g_agg[(size_t)NN * DIN];   // 25.6 MB
__device__ __align__(16) float g_pre[(size_t)NN * DOUT];  // 51.2 MB
__device__ float g_cnt[NN];
__device__ float g_sum[DOUT];
__device__ float g_sqsum[DOUT];
__device__ float g_scale[DOUT];
__device__ float g_shift[DOUT];
__device__ int   g_is64;

// ---------------- helpers -----------------------------------------------------
__device__ __forceinline__ float to_tf32(float v) {
    uint32_t o;                                   // cvt to tf32 needs .b32 dst
    asm("cvt.rna.tf32.f32 %0, %1;" : "=r"(o) : "f"(v));
    return __uint_as_float(o);
}
__device__ __forceinline__ float hi_part(float v) {
    return __uint_as_float(__float_as_uint(v) & 0xFFFFE000u);  // exact in tf32
}

#define MMA_TF32(c, A0, A1, A2, A3, B0, B1)                                  \
    asm volatile(                                                            \
        "mma.sync.aligned.m16n8k8.row.col.f32.tf32.tf32.f32 "                \
        "{%0,%1,%2,%3}, {%4,%5,%6,%7}, {%8,%9}, {%0,%1,%2,%3};"              \
        : "+f"((c)[0]), "+f"((c)[1]), "+f"((c)[2]), "+f"((c)[3])             \
        : "r"(A0), "r"(A1), "r"(A2), "r"(A3), "r"(B0), "r"(B1))

// ---------------- dtype detection for edge_index ----------------------------
__global__ void k_detect(const unsigned* __restrict__ ei) {
    if (threadIdx.x == 0 && blockIdx.x == 0) {
        unsigned acc = 0;
        #pragma unroll
        for (int i = 0; i < 8; i++) acc |= ei[2 * i + 1];
        acc |= ei[2 * EE - 1];
        g_is64 = (acc == 0u) ? 1 : 0;
    }
}

// ---------------- zero scratch ------------------------------------------------
__global__ void k_zero() {
    size_t i = (size_t)blockIdx.x * blockDim.x + threadIdx.x;
    size_t stride = (size_t)gridDim.x * blockDim.x;
    float4 z = make_float4(0.f, 0.f, 0.f, 0.f);
    float4* pa = (float4*)g_agg;
    for (size_t j = i; j < (size_t)NN * (DIN / 4); j += stride) pa[j] = z;
    for (size_t j = i; j < NN; j += stride) g_cnt[j] = 0.f;
    if (i < DOUT) { g_sum[i] = 0.f; g_sqsum[i] = 0.f; }
}

// ---------------- edge scatter: warp per edge, red.v4 ------------------------
__global__ __launch_bounds__(256) void k_scatter(const void* __restrict__ eiv,
                                                 const float* __restrict__ x) {
    int w = (int)((blockIdx.x * blockDim.x + threadIdx.x) >> 5);
    int lane = threadIdx.x & 31;
    if (w >= EE) return;
    int s, d;
    if (g_is64) {
        const long long* ei = (const long long*)eiv;
        s = (int)ei[w];
        d = (int)ei[EE + w];
    } else {
        const int* ei = (const int*)eiv;
        s = ei[w];
        d = ei[EE + w];
    }
    float4 v = __ldg((const float4*)x + (size_t)s * (DIN / 4) + lane);
    float* dst = g_agg + (size_t)d * DIN + lane * 4;
    asm volatile("red.global.add.v4.f32 [%0], {%1,%2,%3,%4};"
                 :: "l"(dst), "f"(v.x), "f"(v.y), "f"(v.z), "f"(v.w) : "memory");
    if (lane == 0) {
        float* c = g_cnt + d;
        asm volatile("red.global.add.f32 [%0], %1;" :: "l"(c), "f"(1.0f) : "memory");
    }
}

// store one 8-k group (v0 = k0..3, v1 = k4..7) as (k,k+4) float2 pairs
__device__ __forceinline__ void store_pairs(float* base, float4 v0, float4 v1) {
    *(float2*)(base + 0) = make_float2(v0.x, v1.x);
    *(float2*)(base + 2) = make_float2(v0.y, v1.y);
    *(float2*)(base + 4) = make_float2(v0.z, v1.z);
    *(float2*)(base + 6) = make_float2(v0.w, v1.w);
}
__device__ __forceinline__ float4 hi4(float4 v) {
    return make_float4(hi_part(v.x), hi_part(v.y), hi_part(v.z), hi_part(v.w));
}
__device__ __forceinline__ float4 sub4(float4 v, float4 h) {
    return make_float4(v.x - h.x, v.y - h.y, v.z - h.z, v.w - h.w);
}
__device__ __forceinline__ float4 rna4(float4 v) {
    return make_float4(to_tf32(v.x), to_tf32(v.y), to_tf32(v.z), to_tf32(v.w));
}

// ---------------- kernel 1: pre = agg_mean@Wl^T + x@Wr^T (tf32 mma, split A) --
// dynamic smem: 4 A-tiles (Ahi, Alo, Xhi, Xlo) + 2 B-tiles (Wl, Wr) = 80 KB
#define SM1_BYTES ((4 * A_TILE_F + 2 * B_TILE_F) * 4)

__global__ __launch_bounds__(256, 1) void k_mma_pre(
    const float* __restrict__ x, const float* __restrict__ Wl,
    const float* __restrict__ Wr)
{
    extern __shared__ float sm[];
    float* sA = sm;                    // 4 * A_TILE_F
    float* sB = sm + 4 * A_TILE_F;     // 2 * B_TILE_F

    const int tid = threadIdx.x;
    const int warp = tid >> 5, lane = tid & 31;
    const int wm = warp >> 2, wn = warp & 3;          // 2 x 4 warp grid
    const int g = lane >> 2, t = lane & 3;
    const int row0 = blockIdx.x * MTILE;

    // loader assignment
    const int lrow = tid >> 1;        // 0..127
    const int lgrp = tid & 1;         // which 8-k group
    int arow = row0 + lrow; if (arow >= NN) arow = NN - 1;
    const float inv = 1.0f / fmaxf(g_cnt[arow], 1.0f);
    const float* pAg = g_agg + (size_t)arow * DIN + lgrp * 8;
    const float* pAx = x + (size_t)arow * DIN + lgrp * 8;
    const float* pWl = Wl + (size_t)tid * DIN;
    const float* pWr = Wr + (size_t)tid * DIN;
    float* sA_base = sA + lrow * SROW + lgrp * 8;
    float* sB_l = sB + tid * SROW;
    float* sB_r = sB + B_TILE_F + tid * SROW;

    float acc[4][8][4];
    #pragma unroll
    for (int mt = 0; mt < 4; mt++)
        #pragma unroll
        for (int nt = 0; nt < 8; nt++)
            #pragma unroll
            for (int q = 0; q < 4; q++) acc[mt][nt][q] = 0.f;

    for (int c = 0; c < 8; c++) {
        const int kc = c * 16;
        __syncthreads();
        // ---- A side: agg*inv and x, hi/lo split ----
        {
            float4 v0 = *(const float4*)(pAg + kc);
            float4 v1 = *(const float4*)(pAg + kc + 4);
            v0.x *= inv; v0.y *= inv; v0.z *= inv; v0.w *= inv;
            v1.x *= inv; v1.y *= inv; v1.z *= inv; v1.w *= inv;
            float4 h0 = hi4(v0), h1 = hi4(v1);
            store_pairs(sA_base, h0, h1);
            store_pairs(sA_base + A_TILE_F, sub4(v0, h0), sub4(v1, h1));
            float4 u0 = *(const float4*)(pAx + kc);
            float4 u1 = *(const float4*)(pAx + kc + 4);
            h0 = hi4(u0); h1 = hi4(u1);
            store_pairs(sA_base + 2 * A_TILE_F, h0, h1);
            store_pairs(sA_base + 3 * A_TILE_F, sub4(u0, h0), sub4(u1, h1));
        }
        // ---- B side: Wl / Wr rounded to tf32 ----
        #pragma unroll
        for (int g2 = 0; g2 < 2; g2++) {
            float4 w0 = rna4(*(const float4*)(pWl + kc + g2 * 8));
            float4 w1 = rna4(*(const float4*)(pWl + kc + g2 * 8 + 4));
            store_pairs(sB_l + g2 * 8, w0, w1);
            float4 r0 = rna4(*(const float4*)(pWr + kc + g2 * 8));
            float4 r1 = rna4(*(const float4*)(pWr + kc + g2 * 8 + 4));
            store_pairs(sB_r + g2 * 8, r0, r1);
        }
        __syncthreads();
        // ---- 4 MMA chains: Ahi*Bl, Alo*Bl, Xhi*Br, Xlo*Br ----
        #pragma unroll
        for (int ch = 0; ch < 4; ch++) {
            const float* At = sA + ch * A_TILE_F;
            const float* Bt = sB + (ch >> 1) * B_TILE_F;
            #pragma unroll
            for (int ks = 0; ks < 2; ks++) {
                const int kb = ks * 8 + 2 * t;
                float2 fa0[4], fa1[4], fb[8];
                #pragma unroll
                for (int mt = 0; mt < 4; mt++) {
                    int r = wm * 64 + mt * 16 + g;
                    fa0[mt] = *(const float2*)&At[r * SROW + kb];
                    fa1[mt] = *(const float2*)&At[(r + 8) * SROW + kb];
                }
                #pragma unroll
                for (int nt = 0; nt < 8; nt++) {
                    int n = wn * 64 + nt * 8 + g;
                    fb[nt] = *(const float2*)&Bt[n * SROW + kb];
                }
                #pragma unroll
                for (int mt = 0; mt < 4; mt++)
                    #pragma unroll
                    for (int nt = 0; nt < 8; nt++)
                        MMA_TF32(acc[mt][nt],
                                 __float_as_uint(fa0[mt].x), __float_as_uint(fa1[mt].x),
                                 __float_as_uint(fa0[mt].y), __float_as_uint(fa1[mt].y),
                                 __float_as_uint(fb[nt].x),  __float_as_uint(fb[nt].y));
            }
        }
    }

    // ---- epilogue: write g_pre ----
    #pragma unroll
    for (int mt = 0; mt < 4; mt++) {
        int ra = row0 + wm * 64 + mt * 16 + g;
        int rb = ra + 8;
        #pragma unroll
        for (int nt = 0; nt < 8; nt++) {
            int col = wn * 64 + nt * 8 + 2 * t;
            if (ra < NN)
                *(float2*)&g_pre[(size_t)ra * DOUT + col] =
                    make_float2(acc[mt][nt][0], acc[mt][nt][1]);
            if (rb < NN)
                *(float2*)&g_pre[(size_t)rb * DOUT + col] =
                    make_float2(acc[mt][nt][2], acc[mt][nt][3]);
        }
    }
}

// ---------------- BN column stats over pre -----------------------------------
__global__ __launch_bounds__(256) void k_colstats() {
    int col = threadIdx.x;
    int r0 = blockIdx.x * 64;
    int rend = min(r0 + 64, NN);
    float s = 0.f, q = 0.f;
    for (int r = r0; r < rend; r++) {
        float v = g_pre[(size_t)r * DOUT + col];
        s += v; q += v * v;
    }
    atomicAdd(&g_sum[col], s);
    atomicAdd(&g_sqsum[col], q);
}

__global__ void k_stats(const float* __restrict__ gamma, const float* __restrict__ beta) {
    int j = threadIdx.x;
    const float invN = 1.0f / (float)NN;
    float mean = g_sum[j] * invN;
    float var = g_sqsum[j] * invN - mean * mean;
    float rstd = rsqrtf(var + BN_EPS);
    float sc = rstd * gamma[j];
    g_scale[j] = sc;
    g_shift[j] = beta[j] - mean * sc;
}

// ---------------- kernel 2: id = x@Wres^T, fused BN/ReLU/add -----------------
#define SM2_BYTES ((2 * A_TILE_F + B_TILE_F) * 4)

__global__ __launch_bounds__(256, 1) void k_mma_fin(
    const float* __restrict__ x, const float* __restrict__ Wres,
    const float* __restrict__ bres, float* __restrict__ out)
{
    extern __shared__ float sm[];
    __shared__ float sSc[DOUT], sSh[DOUT], sBr[DOUT];
    float* sA = sm;                    // 2 * A_TILE_F (Xhi, Xlo)
    float* sB = sm + 2 * A_TILE_F;     // B_TILE_F

    const int tid = threadIdx.x;
    const int warp = tid >> 5, lane = tid & 31;
    const int wm = warp >> 2, wn = warp & 3;
    const int g = lane >> 2, t = lane & 3;
    const int row0 = blockIdx.x * MTILE;

    sSc[tid] = g_scale[tid]; sSh[tid] = g_shift[tid]; sBr[tid] = __ldg(&bres[tid]);

    const int lrow = tid >> 1;
    const int lgrp = tid & 1;
    int arow = row0 + lrow; if (arow >= NN) arow = NN - 1;
    const float* pAx = x + (size_t)arow * DIN + lgrp * 8;
    const float* pW = Wres + (size_t)tid * DIN;
    float* sA_base = sA + lrow * SROW + lgrp * 8;
    float* sB_base = sB + tid * SROW;

    float acc[4][8][4];
    #pragma unroll
    for (int mt = 0; mt < 4; mt++)
        #pragma unroll
        for (int nt = 0; nt < 8; nt++)
            #pragma unroll
            for (int q = 0; q < 4; q++) acc[mt][nt][q] = 0.f;

    for (int c = 0; c < 8; c++) {
        const int kc = c * 16;
        __syncthreads();
        {
            float4 u0 = *(const float4*)(pAx + kc);
            float4 u1 = *(const float4*)(pAx + kc + 4);
            float4 h0 = hi4(u0), h1 = hi4(u1);
            store_pairs(sA_base, h0, h1);
            store_pairs(sA_base + A_TILE_F, sub4(u0, h0), sub4(u1, h1));
        }
        #pragma unroll
        for (int g2 = 0; g2 < 2; g2++) {
            float4 w0 = rna4(*(const float4*)(pW + kc + g2 * 8));
            float4 w1 = rna4(*(const float4*)(pW + kc + g2 * 8 + 4));
            store_pairs(sB_base + g2 * 8, w0, w1);
        }
        __syncthreads();
        #pragma unroll
        for (int ch = 0; ch < 2; ch++) {
            const float* At = sA + ch * A_TILE_F;
            #pragma unroll
            for (int ks = 0; ks < 2; ks++) {
                const int kb = ks * 8 + 2 * t;
                float2 fa0[4], fa1[4], fb[8];
                #pragma unroll
                for (int mt = 0; mt < 4; mt++) {
                    int r = wm * 64 + mt * 16 + g;
                    fa0[mt] = *(const float2*)&At[r * SROW + kb];
                    fa1[mt] = *(const float2*)&At[(r + 8) * SROW + kb];
                }
                #pragma unroll
                for (int nt = 0; nt < 8; nt++) {
                    int n = wn * 64 + nt * 8 + g;
                    fb[nt] = *(const float2*)&sB[n * SROW + kb];
                }
                #pragma unroll
                for (int mt = 0; mt < 4; mt++)
                    #pragma unroll
                    for (int nt = 0; nt < 8; nt++)
                        MMA_TF32(acc[mt][nt],
                                 __float_as_uint(fa0[mt].x), __float_as_uint(fa1[mt].x),
                                 __float_as_uint(fa0[mt].y), __float_as_uint(fa1[mt].y),
                                 __float_as_uint(fb[nt].x),  __float_as_uint(fb[nt].y));
            }
        }
    }

    // ---- fused epilogue: out = relu(pre*sc+sh) + acc + bres ----
    #pragma unroll
    for (int mt = 0; mt < 4; mt++) {
        int ra = row0 + wm * 64 + mt * 16 + g;
        int rb = ra + 8;
        #pragma unroll
        for (int nt = 0; nt < 8; nt++) {
            int col = wn * 64 + nt * 8 + 2 * t;
            float sc0 = sSc[col], sc1 = sSc[col + 1];
            float sh0 = sSh[col], sh1 = sSh[col + 1];
            float br0 = sBr[col], br1 = sBr[col + 1];
            if (ra < NN) {
                float2 pv = *(const float2*)&g_pre[(size_t)ra * DOUT + col];
                float2 o;
                o.x = fmaxf(pv.x * sc0 + sh0, 0.f) + acc[mt][nt][0] + br0;
                o.y = fmaxf(pv.y * sc1 + sh1, 0.f) + acc[mt][nt][1] + br1;
                *(float2*)&out[(size_t)ra * DOUT + col] = o;
            }
            if (rb < NN) {
                float2 pv = *(const float2*)&g_pre[(size_t)rb * DOUT + col];
                float2 o;
                o.x = fmaxf(pv.x * sc0 + sh0, 0.f) + acc[mt][nt][2] + br0;
                o.y = fmaxf(pv.y * sc1 + sh1, 0.f) + acc[mt][nt][3] + br1;
                *(float2*)&out[(size_t)rb * DOUT + col] = o;
            }
        }
    }
}

// ---------------- launch ------------------------------------------------------
extern "C" void kernel_launch(void* const* d_in, const int* in_sizes, int n_in,
                              void* d_out, int out_size) {
    const float* x     = (const float*)d_in[0];
    const void*  ei    = d_in[1];
    const float* Wl    = (const float*)d_in[2];
    // d_in[3] = b_l — absorbed by BatchNorm, unused
    const float* Wr    = (const float*)d_in[4];
    const float* Wres  = (const float*)d_in[5];
    const float* bres  = (const float*)d_in[6];
    const float* gamma = (const float*)d_in[7];
    const float* beta  = (const float*)d_in[8];
    float* out = (float*)d_out;

    cudaFuncSetAttribute(k_mma_pre, cudaFuncAttributeMaxDynamicSharedMemorySize, SM1_BYTES);
    cudaFuncSetAttribute(k_mma_fin, cudaFuncAttributeMaxDynamicSharedMemorySize, SM2_BYTES);

    k_detect<<<1, 1>>>((const unsigned*)ei);
    k_zero<<<4096, 256>>>();
    k_scatter<<<(EE + 7) / 8, 256>>>(ei, x);
    k_mma_pre<<<NTILES, 256, SM1_BYTES>>>(x, Wl, Wr);
    k_colstats<<<(NN + 63) / 64, 256>>>();
    k_stats<<<1, DOUT>>>(gamma, beta);
    k_mma_fin<<<NTILES, 256, SM2_BYTES>>>(x, Wres, bres, out);
}

// round 6
// speedup vs baseline: 1.6078x; 1.2784x over previous
#include <cuda_runtime.h>
#include <cstdint>

#define NN   50000
#define EE   640000
#define DIN  128
#define DOUT 256
#define BN_EPS 1e-5f
#define MTILE 128
#define NTILES ((NN + MTILE - 1) / MTILE)   // 391
#define SROW 20                              // row stride in floats (80B, 16B-aligned, conflict-free)

// ---- kernel1 stage layout (floats) ----
#define AG_OFF 0
#define X_OFF  (128 * SROW)
#define WL_OFF (2 * 128 * SROW)
#define WR_OFF (2 * 128 * SROW + 256 * SROW)
#define STAGE_F (2 * 128 * SROW + 2 * 256 * SROW)   // 15360 floats
#define SM1_BYTES (2 * STAGE_F * 4)                 // 122880 B

// ---- kernel2 stage layout ----
#define X2_OFF 0
#define W2_OFF (128 * SROW)
#define STAGE2_F (128 * SROW + 256 * SROW)          // 7680 floats
#define SM2_BYTES (2 * STAGE2_F * 4)                // 61440 B

// ---------------- scratch (static __device__, no allocation) ----------------
__device__ __align__(16) float g_agg[(size_t)NN * DIN];   // 25.6 MB
__device__ __align__(16) float g_pre[(size_t)NN * DOUT];  // 51.2 MB
__device__ float g_cnt[NN];
__device__ float g_sum[DOUT];
__device__ float g_sqsum[DOUT];
__device__ float g_scale[DOUT];
__device__ float g_shift[DOUT];
__device__ int   g_is64;

// ---------------- helpers -----------------------------------------------------
__device__ __forceinline__ float to_tf32(float v) {
    uint32_t o;
    asm("cvt.rna.tf32.f32 %0, %1;" : "=r"(o) : "f"(v));
    return __uint_as_float(o);
}
__device__ __forceinline__ float hi_part(float v) {
    return __uint_as_float(__float_as_uint(v) & 0xFFFFE000u);  // exact in tf32
}
__device__ __forceinline__ void cp16(uint32_t dst, const float* src) {
    asm volatile("cp.async.cg.shared.global [%0], [%1], 16;" :: "r"(dst), "l"(src));
}
#define CP_COMMIT() asm volatile("cp.async.commit_group;" ::: "memory")
#define CP_WAIT1()  asm volatile("cp.async.wait_group 1;" ::: "memory")
#define CP_WAIT0()  asm volatile("cp.async.wait_group 0;" ::: "memory")

#define MMA_TF32(c, A0, A1, A2, A3, B0, B1)                                  \
    asm volatile(                                                            \
        "mma.sync.aligned.m16n8k8.row.col.f32.tf32.tf32.f32 "                \
        "{%0,%1,%2,%3}, {%4,%5,%6,%7}, {%8,%9}, {%0,%1,%2,%3};"              \
        : "+f"((c)[0]), "+f"((c)[1]), "+f"((c)[2]), "+f"((c)[3])             \
        : "r"(__float_as_uint(A0)), "r"(__float_as_uint(A1)),                \
          "r"(__float_as_uint(A2)), "r"(__float_as_uint(A3)),                \
          "r"(__float_as_uint(B0)), "r"(__float_as_uint(B1)))

// ---------------- dtype detection for edge_index ----------------------------
__global__ void k_detect(const unsigned* __restrict__ ei) {
    if (threadIdx.x == 0 && blockIdx.x == 0) {
        unsigned acc = 0;
        #pragma unroll
        for (int i = 0; i < 8; i++) acc |= ei[2 * i + 1];
        acc |= ei[2 * EE - 1];
        g_is64 = (acc == 0u) ? 1 : 0;
    }
}

// ---------------- zero scratch ------------------------------------------------
__global__ void k_zero() {
    size_t i = (size_t)blockIdx.x * blockDim.x + threadIdx.x;
    size_t stride = (size_t)gridDim.x * blockDim.x;
    float4 z = make_float4(0.f, 0.f, 0.f, 0.f);
    float4* pa = (float4*)g_agg;
    for (size_t j = i; j < (size_t)NN * (DIN / 4); j += stride) pa[j] = z;
    for (size_t j = i; j < NN; j += stride) g_cnt[j] = 0.f;
    if (i < DOUT) { g_sum[i] = 0.f; g_sqsum[i] = 0.f; }
}

// ---------------- edge scatter: warp per edge, red.v4 ------------------------
__global__ __launch_bounds__(256) void k_scatter(const void* __restrict__ eiv,
                                                 const float* __restrict__ x) {
    int w = (int)((blockIdx.x * blockDim.x + threadIdx.x) >> 5);
    int lane = threadIdx.x & 31;
    if (w >= EE) return;
    int s, d;
    if (g_is64) {
        const long long* ei = (const long long*)eiv;
        s = (int)ei[w];
        d = (int)ei[EE + w];
    } else {
        const int* ei = (const int*)eiv;
        s = ei[w];
        d = ei[EE + w];
    }
    float4 v = __ldg((const float4*)x + (size_t)s * (DIN / 4) + lane);
    float* dst = g_agg + (size_t)d * DIN + lane * 4;
    asm volatile("red.global.add.v4.f32 [%0], {%1,%2,%3,%4};"
                 :: "l"(dst), "f"(v.x), "f"(v.y), "f"(v.z), "f"(v.w) : "memory");
    if (lane == 0) {
        float* c = g_cnt + d;
        asm volatile("red.global.add.f32 [%0], %1;" :: "l"(c), "f"(1.0f) : "memory");
    }
}

// ---------------- kernel 1: pre = agg_mean@Wl^T + x@Wr^T + fused BN stats ----
// 3 MMA chains: Ahi*Wl, Alo*Wl (exact split of mean), rna(x)*Wr.
// cp.async 2-stage pipeline, raw tiles in smem, conversions in registers.
__global__ __launch_bounds__(256, 1) void k_mma_pre(
    const float* __restrict__ xg, const float* __restrict__ Wl,
    const float* __restrict__ Wr)
{
    extern __shared__ float smf[];
    __shared__ float sInv[128];
    uint32_t sbase = (uint32_t)__cvta_generic_to_shared(smf);

    const int tid = threadIdx.x;
    const int warp = tid >> 5, lane = tid & 31;
    const int wm = warp >> 2, wn = warp & 3;          // 2 x 4 warp grid
    const int g_ = lane >> 2, t_ = lane & 3;
    const int row0 = blockIdx.x * MTILE;

    if (tid < 128) {
        int r = min(row0 + tid, NN - 1);
        sInv[tid] = 1.0f / fmaxf(g_cnt[r], 1.0f);
    }

    auto load_stage = [&](int stg, int kc) {
        uint32_t sb = sbase + stg * (STAGE_F * 4);
        #pragma unroll
        for (int j = 0; j < 12; j++) {
            int i = tid + 256 * j;
            int part = i & 3;
            const float* src;
            uint32_t doff;
            if (j < 2)      { int r = i >> 2;            int gr = min(row0 + r, NN - 1);
                              src = g_agg + (size_t)gr * DIN; doff = AG_OFF + r * SROW; }
            else if (j < 4) { int r = (i >> 2) & 127;    int gr = min(row0 + r, NN - 1);
                              src = xg + (size_t)gr * DIN;    doff = X_OFF + r * SROW; }
            else if (j < 8) { int r = (i - 1024) >> 2;
                              src = Wl + (size_t)r * DIN;     doff = WL_OFF + r * SROW; }
            else            { int r = (i - 2048) >> 2;
                              src = Wr + (size_t)r * DIN;     doff = WR_OFF + r * SROW; }
            cp16(sb + (doff + part * 4) * 4, src + kc + part * 4);
        }
    };

    float acc[4][8][4];
    #pragma unroll
    for (int mt = 0; mt < 4; mt++)
        #pragma unroll
        for (int nt = 0; nt < 8; nt++)
            #pragma unroll
            for (int q = 0; q < 4; q++) acc[mt][nt][q] = 0.f;

    load_stage(0, 0);
    CP_COMMIT();
    __syncthreads();                       // sInv ready (also orders first wait)

    float invA[8];
    #pragma unroll
    for (int mt = 0; mt < 4; mt++) {
        int r = wm * 64 + mt * 16 + g_;
        invA[2 * mt]     = sInv[r];
        invA[2 * mt + 1] = sInv[r + 8];
    }

    for (int c = 0; c < 8; c++) {
        if (c < 7) { load_stage((c + 1) & 1, (c + 1) * 16); CP_COMMIT(); CP_WAIT1(); }
        else       { CP_WAIT0(); }
        __syncthreads();
        const float* st = smf + (c & 1) * STAGE_F;

        #pragma unroll
        for (int ks = 0; ks < 2; ks++) {
            const int kk = ks * 8 + t_;
            float blx[8], bly[8], brx[8], bry[8];
            #pragma unroll
            for (int nt = 0; nt < 8; nt++) {
                int n = wn * 64 + nt * 8 + g_;
                const float* B1 = st + WL_OFF + n * SROW;
                blx[nt] = to_tf32(B1[kk]); bly[nt] = to_tf32(B1[kk + 4]);
                const float* B2 = st + WR_OFF + n * SROW;
                brx[nt] = to_tf32(B2[kk]); bry[nt] = to_tf32(B2[kk + 4]);
            }
            #pragma unroll
            for (int mt = 0; mt < 4; mt++) {
                int r = wm * 64 + mt * 16 + g_;
                const float* A = st + AG_OFF + r * SROW;
                float v0 = A[kk] * invA[2 * mt];
                float v1 = A[8 * SROW + kk] * invA[2 * mt + 1];
                float v2 = A[kk + 4] * invA[2 * mt];
                float v3 = A[8 * SROW + kk + 4] * invA[2 * mt + 1];
                float h0 = hi_part(v0), h1 = hi_part(v1), h2 = hi_part(v2), h3 = hi_part(v3);
                float l0 = v0 - h0, l1 = v1 - h1, l2 = v2 - h2, l3 = v3 - h3;
                const float* X = st + X_OFF + r * SROW;
                float x0 = to_tf32(X[kk]);
                float x1 = to_tf32(X[8 * SROW + kk]);
                float x2 = to_tf32(X[kk + 4]);
                float x3 = to_tf32(X[8 * SROW + kk + 4]);
                #pragma unroll
                for (int nt = 0; nt < 8; nt++) {
                    MMA_TF32(acc[mt][nt], h0, h1, h2, h3, blx[nt], bly[nt]);
                    MMA_TF32(acc[mt][nt], l0, l1, l2, l3, blx[nt], bly[nt]);
                    MMA_TF32(acc[mt][nt], x0, x1, x2, x3, brx[nt], bry[nt]);
                }
            }
        }
        __syncthreads();
    }

    // ---- epilogue: store g_pre + fused BN column stats ----
    float ps[16], pq[16];
    #pragma unroll
    for (int k = 0; k < 16; k++) { ps[k] = 0.f; pq[k] = 0.f; }

    #pragma unroll
    for (int mt = 0; mt < 4; mt++) {
        int ra = row0 + wm * 64 + mt * 16 + g_;
        int rb = ra + 8;
        bool va = ra < NN, vb = rb < NN;
        #pragma unroll
        for (int nt = 0; nt < 8; nt++) {
            int col = wn * 64 + nt * 8 + 2 * t_;
            if (va) {
                *(float2*)&g_pre[(size_t)ra * DOUT + col] =
                    make_float2(acc[mt][nt][0], acc[mt][nt][1]);
                ps[2 * nt]     += acc[mt][nt][0];
                ps[2 * nt + 1] += acc[mt][nt][1];
                pq[2 * nt]     += acc[mt][nt][0] * acc[mt][nt][0];
                pq[2 * nt + 1] += acc[mt][nt][1] * acc[mt][nt][1];
            }
            if (vb) {
                *(float2*)&g_pre[(size_t)rb * DOUT + col] =
                    make_float2(acc[mt][nt][2], acc[mt][nt][3]);
                ps[2 * nt]     += acc[mt][nt][2];
                ps[2 * nt + 1] += acc[mt][nt][3];
                pq[2 * nt]     += acc[mt][nt][2] * acc[mt][nt][2];
                pq[2 * nt + 1] += acc[mt][nt][3] * acc[mt][nt][3];
            }
        }
    }
    // reduce across g (lane bits 2..4), then one atomic per column per warp
    #pragma unroll
    for (int k = 0; k < 16; k++) {
        #pragma unroll
        for (int m = 4; m <= 16; m <<= 1) {
            ps[k] += __shfl_xor_sync(0xffffffffu, ps[k], m);
            pq[k] += __shfl_xor_sync(0xffffffffu, pq[k], m);
        }
    }
    if (g_ == 0) {
        #pragma unroll
        for (int nt = 0; nt < 8; nt++) {
            int col = wn * 64 + nt * 8 + 2 * t_;
            atomicAdd(&g_sum[col],       ps[2 * nt]);
            atomicAdd(&g_sum[col + 1],   ps[2 * nt + 1]);
            atomicAdd(&g_sqsum[col],     pq[2 * nt]);
            atomicAdd(&g_sqsum[col + 1], pq[2 * nt + 1]);
        }
    }
}

// ---------------- BN stats finalize -------------------------------------------
__global__ void k_stats(const float* __restrict__ gamma, const float* __restrict__ beta) {
    int j = threadIdx.x;
    const float invN = 1.0f / (float)NN;
    float mean = g_sum[j] * invN;
    float var = g_sqsum[j] * invN - mean * mean;
    float rstd = rsqrtf(var + BN_EPS);
    float sc = rstd * gamma[j];
    g_scale[j] = sc;
    g_shift[j] = beta[j] - mean * sc;
}

// ---------------- kernel 2: id = x@Wres^T, fused BN/ReLU/add -----------------
__global__ __launch_bounds__(256, 1) void k_mma_fin(
    const float* __restrict__ xg, const float* __restrict__ Wres,
    const float* __restrict__ bres, float* __restrict__ out)
{
    extern __shared__ float smf[];
    __shared__ float sSc[DOUT], sSh[DOUT], sBr[DOUT];
    uint32_t sbase = (uint32_t)__cvta_generic_to_shared(smf);

    const int tid = threadIdx.x;
    const int warp = tid >> 5, lane = tid & 31;
    const int wm = warp >> 2, wn = warp & 3;
    const int g_ = lane >> 2, t_ = lane & 3;
    const int row0 = blockIdx.x * MTILE;

    sSc[tid] = g_scale[tid]; sSh[tid] = g_shift[tid]; sBr[tid] = __ldg(&bres[tid]);

    auto load_stage = [&](int stg, int kc) {
        uint32_t sb = sbase + stg * (STAGE2_F * 4);
        #pragma unroll
        for (int j = 0; j < 6; j++) {
            int i = tid + 256 * j;
            int part = i & 3;
            const float* src;
            uint32_t doff;
            if (j < 2) { int r = i >> 2; int gr = min(row0 + r, NN - 1);
                         src = xg + (size_t)gr * DIN;    doff = X2_OFF + r * SROW; }
            else       { int r = (i - 512) >> 2;
                         src = Wres + (size_t)r * DIN;   doff = W2_OFF + r * SROW; }
            cp16(sb + (doff + part * 4) * 4, src + kc + part * 4);
        }
    };

    float acc[4][8][4];
    #pragma unroll
    for (int mt = 0; mt < 4; mt++)
        #pragma unroll
        for (int nt = 0; nt < 8; nt++)
            #pragma unroll
            for (int q = 0; q < 4; q++) acc[mt][nt][q] = 0.f;

    load_stage(0, 0);
    CP_COMMIT();

    for (int c = 0; c < 8; c++) {
        if (c < 7) { load_stage((c + 1) & 1, (c + 1) * 16); CP_COMMIT(); CP_WAIT1(); }
        else       { CP_WAIT0(); }
        __syncthreads();
        const float* st = smf + (c & 1) * STAGE2_F;

        #pragma unroll
        for (int ks = 0; ks < 2; ks++) {
            const int kk = ks * 8 + t_;
            float bx[8], by[8];
            #pragma unroll
            for (int nt = 0; nt < 8; nt++) {
                int n = wn * 64 + nt * 8 + g_;
                const float* B = st + W2_OFF + n * SROW;
                bx[nt] = to_tf32(B[kk]); by[nt] = to_tf32(B[kk + 4]);
            }
            #pragma unroll
            for (int mt = 0; mt < 4; mt++) {
                int r = wm * 64 + mt * 16 + g_;
                const float* X = st + X2_OFF + r * SROW;
                float x0 = to_tf32(X[kk]);
                float x1 = to_tf32(X[8 * SROW + kk]);
                float x2 = to_tf32(X[kk + 4]);
                float x3 = to_tf32(X[8 * SROW + kk + 4]);
                #pragma unroll
                for (int nt = 0; nt < 8; nt++)
                    MMA_TF32(acc[mt][nt], x0, x1, x2, x3, bx[nt], by[nt]);
            }
        }
        __syncthreads();
    }

    // ---- fused epilogue: out = relu(pre*sc+sh) + acc + bres ----
    #pragma unroll
    for (int mt = 0; mt < 4; mt++) {
        int ra = row0 + wm * 64 + mt * 16 + g_;
        int rb = ra + 8;
        #pragma unroll
        for (int nt = 0; nt < 8; nt++) {
            int col = wn * 64 + nt * 8 + 2 * t_;
            float sc0 = sSc[col], sc1 = sSc[col + 1];
            float sh0 = sSh[col], sh1 = sSh[col + 1];
            float br0 = sBr[col], br1 = sBr[col + 1];
            if (ra < NN) {
                float2 pv = *(const float2*)&g_pre[(size_t)ra * DOUT + col];
                float2 o;
                o.x = fmaxf(pv.x * sc0 + sh0, 0.f) + acc[mt][nt][0] + br0;
                o.y = fmaxf(pv.y * sc1 + sh1, 0.f) + acc[mt][nt][1] + br1;
                *(float2*)&out[(size_t)ra * DOUT + col] = o;
            }
            if (rb < NN) {
                float2 pv = *(const float2*)&g_pre[(size_t)rb * DOUT + col];
                float2 o;
                o.x = fmaxf(pv.x * sc0 + sh0, 0.f) + acc[mt][nt][2] + br0;
                o.y = fmaxf(pv.y * sc1 + sh1, 0.f) + acc[mt][nt][3] + br1;
                *(float2*)&out[(size_t)rb * DOUT + col] = o;
            }
        }
    }
}

// ---------------- launch ------------------------------------------------------
extern "C" void kernel_launch(void* const* d_in, const int* in_sizes, int n_in,
                              void* d_out, int out_size) {
    const float* x     = (const float*)d_in[0];
    const void*  ei    = d_in[1];
    const float* Wl    = (const float*)d_in[2];
    // d_in[3] = b_l — absorbed by BatchNorm, unused
    const float* Wr    = (const float*)d_in[4];
    const float* Wres  = (const float*)d_in[5];
    const float* bres  = (const float*)d_in[6];
    const float* gamma = (const float*)d_in[7];
    const float* beta  = (const float*)d_in[8];
    float* out = (float*)d_out;

    cudaFuncSetAttribute(k_mma_pre, cudaFuncAttributeMaxDynamicSharedMemorySize, SM1_BYTES);
    cudaFuncSetAttribute(k_mma_fin, cudaFuncAttributeMaxDynamicSharedMemorySize, SM2_BYTES);

    k_detect<<<1, 1>>>((const unsigned*)ei);
    k_zero<<<4096, 256>>>();
    k_scatter<<<(EE + 7) / 8, 256>>>(ei, x);
    k_mma_pre<<<NTILES, 256, SM1_BYTES>>>(x, Wl, Wr);
    k_stats<<<1, DOUT>>>(gamma, beta);
    k_mma_fin<<<NTILES, 256, SM2_BYTES>>>(x, Wres, bres, out);
}

// round 7
// speedup vs baseline: 2.1532x; 1.3392x over previous
#include <cuda_runtime.h>
#include <cstdint>

#define NN   50000
#define EE   640000
#define DIN  128
#define DOUT 256
#define BN_EPS 1e-5f
#define MTILE 128
#define NTILES ((NN + MTILE - 1) / MTILE)   // 391
#define SROW 20                              // row stride in floats
#define SCAN_BLK 1024
#define NBLK ((NN + SCAN_BLK - 1) / SCAN_BLK)   // 49

// ---- kernel1 stage layout (floats): 4 tiles of 128 rows x 16 k ----
#define AG_OFF 0
#define X_OFF  (128 * SROW)
#define WL_OFF (2 * 128 * SROW)
#define WR_OFF (3 * 128 * SROW)
#define STAGE_F (4 * 128 * SROW)            // 10240 floats
#define SM1_BYTES (2 * STAGE_F * 4)         // 81920 B

// ---- kernel2 stage layout ----
#define X2_OFF 0
#define W2_OFF (128 * SROW)
#define STAGE2_F (2 * 128 * SROW)           // 5120 floats
#define SM2_BYTES (2 * STAGE2_F * 4)        // 40960 B

// ---------------- scratch (static __device__, no allocation) ----------------
__device__ __align__(16) float g_agg[(size_t)NN * DIN];   // 25.6 MB (stores MEAN)
__device__ __align__(16) float g_pre[(size_t)NN * DOUT];  // 51.2 MB
__device__ int   g_deg[NN];
__device__ int   g_excl[NN];
__device__ int   g_off[NN];
__device__ int   g_cur[NN];
__device__ int   g_bsum[NBLK];
__device__ int   g_csr[EE];
__device__ float g_sum[DOUT];
__device__ float g_sqsum[DOUT];
__device__ float g_scale[DOUT];
__device__ float g_shift[DOUT];
__device__ int   g_is64;

// ---------------- helpers -----------------------------------------------------
__device__ __forceinline__ float to_tf32(float v) {
    uint32_t o;
    asm("cvt.rna.tf32.f32 %0, %1;" : "=r"(o) : "f"(v));
    return __uint_as_float(o);
}
__device__ __forceinline__ float hi_part(float v) {
    return __uint_as_float(__float_as_uint(v) & 0xFFFFE000u);  // exact in tf32
}
__device__ __forceinline__ void cp16(uint32_t dst, const float* src) {
    asm volatile("cp.async.cg.shared.global [%0], [%1], 16;" :: "r"(dst), "l"(src));
}
#define CP_COMMIT() asm volatile("cp.async.commit_group;" ::: "memory")
#define CP_WAIT1()  asm volatile("cp.async.wait_group 1;" ::: "memory")
#define CP_WAIT0()  asm volatile("cp.async.wait_group 0;" ::: "memory")

#define MMA_TF32(c, A0, A1, A2, A3, B0, B1)                                  \
    asm volatile(                                                            \
        "mma.sync.aligned.m16n8k8.row.col.f32.tf32.tf32.f32 "                \
        "{%0,%1,%2,%3}, {%4,%5,%6,%7}, {%8,%9}, {%0,%1,%2,%3};"              \
        : "+f"((c)[0]), "+f"((c)[1]), "+f"((c)[2]), "+f"((c)[3])             \
        : "r"(__float_as_uint(A0)), "r"(__float_as_uint(A1)),                \
          "r"(__float_as_uint(A2)), "r"(__float_as_uint(A3)),                \
          "r"(__float_as_uint(B0)), "r"(__float_as_uint(B1)))

__device__ __forceinline__ int load_dst(const void* eiv, int e) {
    return g_is64 ? (int)((const long long*)eiv)[EE + e] : ((const int*)eiv)[EE + e];
}
__device__ __forceinline__ int load_src(const void* eiv, int e) {
    return g_is64 ? (int)((const long long*)eiv)[e] : ((const int*)eiv)[e];
}

// ---------------- dtype detection for edge_index ----------------------------
__global__ void k_detect(const unsigned* __restrict__ ei) {
    if (threadIdx.x == 0 && blockIdx.x == 0) {
        unsigned acc = 0;
        #pragma unroll
        for (int i = 0; i < 8; i++) acc |= ei[2 * i + 1];
        acc |= ei[2 * EE - 1];
        g_is64 = (acc == 0u) ? 1 : 0;
    }
}

// ---------------- zero small arrays ------------------------------------------
__global__ void k_zinit() {
    int i = blockIdx.x * blockDim.x + threadIdx.x;
    int stride = gridDim.x * blockDim.x;
    for (int j = i; j < NN; j += stride) g_deg[j] = 0;
    if (i < DOUT) { g_sum[i] = 0.f; g_sqsum[i] = 0.f; }
}

// ---------------- CSR build ---------------------------------------------------
__global__ __launch_bounds__(256) void k_hist(const void* __restrict__ eiv) {
    int e = blockIdx.x * blockDim.x + threadIdx.x;
    if (e >= EE) return;
    atomicAdd(&g_deg[load_dst(eiv, e)], 1);
}

__global__ __launch_bounds__(SCAN_BLK) void k_scan1() {
    __shared__ int s[SCAN_BLK];
    int i = blockIdx.x * SCAN_BLK + threadIdx.x;
    int v = (i < NN) ? g_deg[i] : 0;
    s[threadIdx.x] = v;
    __syncthreads();
    for (int off = 1; off < SCAN_BLK; off <<= 1) {
        int t = (threadIdx.x >= off) ? s[threadIdx.x - off] : 0;
        __syncthreads();
        s[threadIdx.x] += t;
        __syncthreads();
    }
    if (i < NN) g_excl[i] = s[threadIdx.x] - v;
    if (threadIdx.x == SCAN_BLK - 1) g_bsum[blockIdx.x] = s[SCAN_BLK - 1];
}

__global__ void k_scan2() {
    if (threadIdx.x == 0) {
        int a = 0;
        for (int i = 0; i < NBLK; i++) { int t = g_bsum[i]; g_bsum[i] = a; a += t; }
    }
}

__global__ void k_scan3() {
    int i = blockIdx.x * blockDim.x + threadIdx.x;
    if (i >= NN) return;
    int o = g_excl[i] + g_bsum[i / SCAN_BLK];
    g_off[i] = o;
    g_cur[i] = o;
}

__global__ __launch_bounds__(256) void k_fill(const void* __restrict__ eiv) {
    int e = blockIdx.x * blockDim.x + threadIdx.x;
    if (e >= EE) return;
    int d = load_dst(eiv, e);
    int pos = atomicAdd(&g_cur[d], 1);
    g_csr[pos] = load_src(eiv, e);
}

// ---------------- gather: warp per node, writes MEAN into g_agg ---------------
__global__ __launch_bounds__(256) void k_gather(const float* __restrict__ x) {
    int node = (int)((blockIdx.x * blockDim.x + threadIdx.x) >> 5);
    int lane = threadIdx.x & 31;
    if (node >= NN) return;
    int start = g_off[node];
    int deg = g_deg[node];
    float4 acc = make_float4(0.f, 0.f, 0.f, 0.f);
    int j = 0;
    for (; j + 4 <= deg; j += 4) {
        int s0 = g_csr[start + j], s1 = g_csr[start + j + 1];
        int s2 = g_csr[start + j + 2], s3 = g_csr[start + j + 3];
        float4 v0 = __ldg((const float4*)x + (size_t)s0 * 32 + lane);
        float4 v1 = __ldg((const float4*)x + (size_t)s1 * 32 + lane);
        float4 v2 = __ldg((const float4*)x + (size_t)s2 * 32 + lane);
        float4 v3 = __ldg((const float4*)x + (size_t)s3 * 32 + lane);
        acc.x += v0.x + v1.x + v2.x + v3.x;
        acc.y += v0.y + v1.y + v2.y + v3.y;
        acc.z += v0.z + v1.z + v2.z + v3.z;
        acc.w += v0.w + v1.w + v2.w + v3.w;
    }
    for (; j < deg; j++) {
        int s = g_csr[start + j];
        float4 v = __ldg((const float4*)x + (size_t)s * 32 + lane);
        acc.x += v.x; acc.y += v.y; acc.z += v.z; acc.w += v.w;
    }
    float inv = 1.0f / fmaxf((float)deg, 1.0f);
    acc.x *= inv; acc.y *= inv; acc.z *= inv; acc.w *= inv;
    ((float4*)g_agg)[(size_t)node * 32 + lane] = acc;
}

// ---------------- kernel 1: pre = agg@Wl^T + x@Wr^T + fused BN stats ---------
// 128x128 tile per block, grid (NTILES, 2). 3 chains: Ahi*Wl, Alo*Wl, rna(x)*Wr.
__global__ __launch_bounds__(256, 2) void k_mma_pre(
    const float* __restrict__ xg, const float* __restrict__ Wl,
    const float* __restrict__ Wr)
{
    extern __shared__ float smf[];
    uint32_t sbase = (uint32_t)__cvta_generic_to_shared(smf);

    const int tid = threadIdx.x;
    const int warp = tid >> 5, lane = tid & 31;
    const int wm = warp >> 2, wn = warp & 3;          // 2 x 4 warp grid (64x32 warp tile)
    const int g_ = lane >> 2, t_ = lane & 3;
    const int row0 = blockIdx.x * MTILE;
    const int col0 = blockIdx.y * 128;

    auto load_stage = [&](int stg, int kc) {
        uint32_t sb = sbase + stg * (STAGE_F * 4);
        #pragma unroll
        for (int j = 0; j < 8; j++) {
            int i = tid + 256 * j;
            int part = i & 3;
            int r = (i >> 2) & 127;
            const float* src;
            uint32_t doff;
            if (j < 2)      { int gr = min(row0 + r, NN - 1);
                              src = g_agg + (size_t)gr * DIN;          doff = AG_OFF + r * SROW; }
            else if (j < 4) { int gr = min(row0 + r, NN - 1);
                              src = xg + (size_t)gr * DIN;             doff = X_OFF + r * SROW; }
            else if (j < 6) { src = Wl + (size_t)(col0 + r) * DIN;     doff = WL_OFF + r * SROW; }
            else            { src = Wr + (size_t)(col0 + r) * DIN;     doff = WR_OFF + r * SROW; }
            cp16(sb + (doff + part * 4) * 4, src + kc + part * 4);
        }
    };

    float acc[4][4][4];
    #pragma unroll
    for (int mt = 0; mt < 4; mt++)
        #pragma unroll
        for (int nt = 0; nt < 4; nt++)
            #pragma unroll
            for (int q = 0; q < 4; q++) acc[mt][nt][q] = 0.f;

    load_stage(0, 0);
    CP_COMMIT();

    for (int c = 0; c < 8; c++) {
        if (c < 7) { load_stage((c + 1) & 1, (c + 1) * 16); CP_COMMIT(); CP_WAIT1(); }
        else       { CP_WAIT0(); }
        __syncthreads();
        const float* st = smf + (c & 1) * STAGE_F;

        #pragma unroll
        for (int ks = 0; ks < 2; ks++) {
            const int kk = ks * 8 + t_;
            float blx[4], bly[4], brx[4], bry[4];
            #pragma unroll
            for (int nt = 0; nt < 4; nt++) {
                int n = wn * 32 + nt * 8 + g_;
                const float* B1 = st + WL_OFF + n * SROW;
                blx[nt] = to_tf32(B1[kk]); bly[nt] = to_tf32(B1[kk + 4]);
                const float* B2 = st + WR_OFF + n * SROW;
                brx[nt] = to_tf32(B2[kk]); bry[nt] = to_tf32(B2[kk + 4]);
            }
            #pragma unroll
            for (int mt = 0; mt < 4; mt++) {
                int r = wm * 64 + mt * 16 + g_;
                const float* A = st + AG_OFF + r * SROW;
                float v0 = A[kk];
                float v1 = A[8 * SROW + kk];
                float v2 = A[kk + 4];
                float v3 = A[8 * SROW + kk + 4];
                float h0 = hi_part(v0), h1 = hi_part(v1), h2 = hi_part(v2), h3 = hi_part(v3);
                float l0 = v0 - h0, l1 = v1 - h1, l2 = v2 - h2, l3 = v3 - h3;
                const float* X = st + X_OFF + r * SROW;
                float x0 = to_tf32(X[kk]);
                float x1 = to_tf32(X[8 * SROW + kk]);
                float x2 = to_tf32(X[kk + 4]);
                float x3 = to_tf32(X[8 * SROW + kk + 4]);
                #pragma unroll
                for (int nt = 0; nt < 4; nt++) {
                    MMA_TF32(acc[mt][nt], h0, h1, h2, h3, blx[nt], bly[nt]);
                    MMA_TF32(acc[mt][nt], l0, l1, l2, l3, blx[nt], bly[nt]);
                    MMA_TF32(acc[mt][nt], x0, x1, x2, x3, brx[nt], bry[nt]);
                }
            }
        }
        __syncthreads();
    }

    // ---- epilogue: store g_pre + fused BN column stats ----
    float ps[8], pq[8];
    #pragma unroll
    for (int k = 0; k < 8; k++) { ps[k] = 0.f; pq[k] = 0.f; }

    #pragma unroll
    for (int mt = 0; mt < 4; mt++) {
        int ra = row0 + wm * 64 + mt * 16 + g_;
        int rb = ra + 8;
        bool va = ra < NN, vb = rb < NN;
        #pragma unroll
        for (int nt = 0; nt < 4; nt++) {
            int col = col0 + wn * 32 + nt * 8 + 2 * t_;
            if (va) {
                *(float2*)&g_pre[(size_t)ra * DOUT + col] =
                    make_float2(acc[mt][nt][0], acc[mt][nt][1]);
                ps[2 * nt]     += acc[mt][nt][0];
                ps[2 * nt + 1] += acc[mt][nt][1];
                pq[2 * nt]     += acc[mt][nt][0] * acc[mt][nt][0];
                pq[2 * nt + 1] += acc[mt][nt][1] * acc[mt][nt][1];
            }
            if (vb) {
                *(float2*)&g_pre[(size_t)rb * DOUT + col] =
                    make_float2(acc[mt][nt][2], acc[mt][nt][3]);
                ps[2 * nt]     += acc[mt][nt][2];
                ps[2 * nt + 1] += acc[mt][nt][3];
                pq[2 * nt]     += acc[mt][nt][2] * acc[mt][nt][2];
                pq[2 * nt + 1] += acc[mt][nt][3] * acc[mt][nt][3];
            }
        }
    }
    #pragma unroll
    for (int k = 0; k < 8; k++) {
        #pragma unroll
        for (int m = 4; m <= 16; m <<= 1) {
            ps[k] += __shfl_xor_sync(0xffffffffu, ps[k], m);
            pq[k] += __shfl_xor_sync(0xffffffffu, pq[k], m);
        }
    }
    if (g_ == 0) {
        #pragma unroll
        for (int nt = 0; nt < 4; nt++) {
            int col = col0 + wn * 32 + nt * 8 + 2 * t_;
            atomicAdd(&g_sum[col],       ps[2 * nt]);
            atomicAdd(&g_sum[col + 1],   ps[2 * nt + 1]);
            atomicAdd(&g_sqsum[col],     pq[2 * nt]);
            atomicAdd(&g_sqsum[col + 1], pq[2 * nt + 1]);
        }
    }
}

// ---------------- BN stats finalize -------------------------------------------
__global__ void k_stats(const float* __restrict__ gamma, const float* __restrict__ beta) {
    int j = threadIdx.x;
    const float invN = 1.0f / (float)NN;
    float mean = g_sum[j] * invN;
    float var = g_sqsum[j] * invN - mean * mean;
    float rstd = rsqrtf(var + BN_EPS);
    float sc = rstd * gamma[j];
    g_scale[j] = sc;
    g_shift[j] = beta[j] - mean * sc;
}

// ---------------- kernel 2: id = x@Wres^T, fused BN/ReLU/add -----------------
__global__ __launch_bounds__(256, 2) void k_mma_fin(
    const float* __restrict__ xg, const float* __restrict__ Wres,
    const float* __restrict__ bres, float* __restrict__ out)
{
    extern __shared__ float smf[];
    __shared__ float sSc[128], sSh[128], sBr[128];
    uint32_t sbase = (uint32_t)__cvta_generic_to_shared(smf);

    const int tid = threadIdx.x;
    const int warp = tid >> 5, lane = tid & 31;
    const int wm = warp >> 2, wn = warp & 3;
    const int g_ = lane >> 2, t_ = lane & 3;
    const int row0 = blockIdx.x * MTILE;
    const int col0 = blockIdx.y * 128;

    if (tid < 128) {
        sSc[tid] = g_scale[col0 + tid];
        sSh[tid] = g_shift[col0 + tid];
        sBr[tid] = __ldg(&bres[col0 + tid]);
    }

    auto load_stage = [&](int stg, int kc) {
        uint32_t sb = sbase + stg * (STAGE2_F * 4);
        #pragma unroll
        for (int j = 0; j < 4; j++) {
            int i = tid + 256 * j;
            int part = i & 3;
            int r = (i >> 2) & 127;
            const float* src;
            uint32_t doff;
            if (j < 2) { int gr = min(row0 + r, NN - 1);
                         src = xg + (size_t)gr * DIN;             doff = X2_OFF + r * SROW; }
            else       { src = Wres + (size_t)(col0 + r) * DIN;   doff = W2_OFF + r * SROW; }
            cp16(sb + (doff + part * 4) * 4, src + kc + part * 4);
        }
    };

    float acc[4][4][4];
    #pragma unroll
    for (int mt = 0; mt < 4; mt++)
        #pragma unroll
        for (int nt = 0; nt < 4; nt++)
            #pragma unroll
            for (int q = 0; q < 4; q++) acc[mt][nt][q] = 0.f;

    load_stage(0, 0);
    CP_COMMIT();

    for (int c = 0; c < 8; c++) {
        if (c < 7) { load_stage((c + 1) & 1, (c + 1) * 16); CP_COMMIT(); CP_WAIT1(); }
        else       { CP_WAIT0(); }
        __syncthreads();
        const float* st = smf + (c & 1) * STAGE2_F;

        #pragma unroll
        for (int ks = 0; ks < 2; ks++) {
            const int kk = ks * 8 + t_;
            float bx[4], by[4];
            #pragma unroll
            for (int nt = 0; nt < 4; nt++) {
                int n = wn * 32 + nt * 8 + g_;
                const float* B = st + W2_OFF + n * SROW;
                bx[nt] = to_tf32(B[kk]); by[nt] = to_tf32(B[kk + 4]);
            }
            #pragma unroll
            for (int mt = 0; mt < 4; mt++) {
                int r = wm * 64 + mt * 16 + g_;
                const float* X = st + X2_OFF + r * SROW;
                float x0 = to_tf32(X[kk]);
                float x1 = to_tf32(X[8 * SROW + kk]);
                float x2 = to_tf32(X[kk + 4]);
                float x3 = to_tf32(X[8 * SROW + kk + 4]);
                #pragma unroll
                for (int nt = 0; nt < 4; nt++)
                    MMA_TF32(acc[mt][nt], x0, x1, x2, x3, bx[nt], by[nt]);
            }
        }
        __syncthreads();
    }

    // ---- fused epilogue: out = relu(pre*sc+sh) + acc + bres ----
    #pragma unroll
    for (int mt = 0; mt < 4; mt++) {
        int ra = row0 + wm * 64 + mt * 16 + g_;
        int rb = ra + 8;
        #pragma unroll
        for (int nt = 0; nt < 4; nt++) {
            int lcol = wn * 32 + nt * 8 + 2 * t_;
            int col = col0 + lcol;
            float sc0 = sSc[lcol], sc1 = sSc[lcol + 1];
            float sh0 = sSh[lcol], sh1 = sSh[lcol + 1];
            float br0 = sBr[lcol], br1 = sBr[lcol + 1];
            if (ra < NN) {
                float2 pv = *(const float2*)&g_pre[(size_t)ra * DOUT + col];
                float2 o;
                o.x = fmaxf(pv.x * sc0 + sh0, 0.f) + acc[mt][nt][0] + br0;
                o.y = fmaxf(pv.y * sc1 + sh1, 0.f) + acc[mt][nt][1] + br1;
                *(float2*)&out[(size_t)ra * DOUT + col] = o;
            }
            if (rb < NN) {
                float2 pv = *(const float2*)&g_pre[(size_t)rb * DOUT + col];
                float2 o;
                o.x = fmaxf(pv.x * sc0 + sh0, 0.f) + acc[mt][nt][2] + br0;
                o.y = fmaxf(pv.y * sc1 + sh1, 0.f) + acc[mt][nt][3] + br1;
                *(float2*)&out[(size_t)rb * DOUT + col] = o;
            }
        }
    }
}

// ---------------- launch ------------------------------------------------------
extern "C" void kernel_launch(void* const* d_in, const int* in_sizes, int n_in,
                              void* d_out, int out_size) {
    const float* x     = (const float*)d_in[0];
    const void*  ei    = d_in[1];
    const float* Wl    = (const float*)d_in[2];
    // d_in[3] = b_l — absorbed by BatchNorm, unused
    const float* Wr    = (const float*)d_in[4];
    const float* Wres  = (const float*)d_in[5];
    const float* bres  = (const float*)d_in[6];
    const float* gamma = (const float*)d_in[7];
    const float* beta  = (const float*)d_in[8];
    float* out = (float*)d_out;

    cudaFuncSetAttribute(k_mma_pre, cudaFuncAttributeMaxDynamicSharedMemorySize, SM1_BYTES);
    cudaFuncSetAttribute(k_mma_fin, cudaFuncAttributeMaxDynamicSharedMemorySize, SM2_BYTES);

    k_detect<<<1, 1>>>((const unsigned*)ei);
    k_zinit<<<64, 1024>>>();
    k_hist<<<(EE + 255) / 256, 256>>>(ei);
    k_scan1<<<NBLK, SCAN_BLK>>>();
    k_scan2<<<1, 32>>>();
    k_scan3<<<(NN + 255) / 256, 256>>>();
    k_fill<<<(EE + 255) / 256, 256>>>(ei);
    k_gather<<<(NN * 32 + 255) / 256, 256>>>(x);
    dim3 g1(NTILES, 2);
    k_mma_pre<<<g1, 256, SM1_BYTES>>>(x, Wl, Wr);
    k_stats<<<1, DOUT>>>(gamma, beta);
    k_mma_fin<<<g1, 256, SM2_BYTES>>>(x, Wres, bres, out);
}

// round 8
// speedup vs baseline: 2.3333x; 1.0837x over previous
#include <cuda_runtime.h>
#include <cstdint>

#define NN   50000
#define EE   640000
#define DIN  128
#define DOUT 256
#define BN_EPS 1e-5f
#define MTILE 128
#define NTILES ((NN + MTILE - 1) / MTILE)   // 391
#define SROW 20                              // row stride in floats
#define SCAN_BLK 1024
#define NBLK ((NN + SCAN_BLK - 1) / SCAN_BLK)   // 49

// ---- kernel1 stage layout (floats): 4 tiles of 128 rows x 16 k ----
#define AG_OFF 0
#define X_OFF  (128 * SROW)
#define WL_OFF (2 * 128 * SROW)
#define WR_OFF (3 * 128 * SROW)
#define STAGE_F (4 * 128 * SROW)            // 10240 floats
#define SM1_BYTES (2 * STAGE_F * 4)         // 81920 B

// ---- kernel2 stage layout ----
#define X2_OFF 0
#define W2_OFF (128 * SROW)
#define STAGE2_F (2 * 128 * SROW)           // 5120 floats
#define SM2_BYTES (2 * STAGE2_F * 4)        // 40960 B

// ---------------- scratch (static __device__, no allocation) ----------------
__device__ __align__(16) float g_agg[(size_t)NN * DIN];   // 25.6 MB (stores MEAN)
__device__ __align__(16) float g_pre[(size_t)NN * DOUT];  // 51.2 MB
__device__ int   g_deg[NN];
__device__ int   g_excl[NN];
__device__ int   g_off[NN];
__device__ int   g_cur[NN];
__device__ int   g_bsum[NBLK];
__device__ int   g_csr[EE];
__device__ float g_sum[DOUT];
__device__ float g_sqsum[DOUT];
__device__ float g_scale[DOUT];
__device__ float g_shift[DOUT];
__device__ int   g_is64;

// ---------------- helpers -----------------------------------------------------
__device__ __forceinline__ float to_tf32(float v) {
    uint32_t o;
    asm("cvt.rna.tf32.f32 %0, %1;" : "=r"(o) : "f"(v));
    return __uint_as_float(o);
}
__device__ __forceinline__ void cp16(uint32_t dst, const float* src) {
    asm volatile("cp.async.cg.shared.global [%0], [%1], 16;" :: "r"(dst), "l"(src));
}
#define CP_COMMIT() asm volatile("cp.async.commit_group;" ::: "memory")
#define CP_WAIT1()  asm volatile("cp.async.wait_group 1;" ::: "memory")
#define CP_WAIT0()  asm volatile("cp.async.wait_group 0;" ::: "memory")

#define MMA_TF32(c, A0, A1, A2, A3, B0, B1)                                  \
    asm volatile(                                                            \
        "mma.sync.aligned.m16n8k8.row.col.f32.tf32.tf32.f32 "                \
        "{%0,%1,%2,%3}, {%4,%5,%6,%7}, {%8,%9}, {%0,%1,%2,%3};"              \
        : "+f"((c)[0]), "+f"((c)[1]), "+f"((c)[2]), "+f"((c)[3])             \
        : "r"(__float_as_uint(A0)), "r"(__float_as_uint(A1)),                \
          "r"(__float_as_uint(A2)), "r"(__float_as_uint(A3)),                \
          "r"(__float_as_uint(B0)), "r"(__float_as_uint(B1)))

__device__ __forceinline__ int load_dst(const void* eiv, int e) {
    return g_is64 ? (int)((const long long*)eiv)[EE + e] : ((const int*)eiv)[EE + e];
}
__device__ __forceinline__ int load_src(const void* eiv, int e) {
    return g_is64 ? (int)((const long long*)eiv)[e] : ((const int*)eiv)[e];
}

// ---------------- init: dtype detect + zero small arrays ---------------------
__global__ void k_init(const unsigned* __restrict__ ei) {
    int i = blockIdx.x * blockDim.x + threadIdx.x;
    if (i == 0) {
        unsigned acc = 0;
        #pragma unroll
        for (int k = 0; k < 8; k++) acc |= ei[2 * k + 1];
        acc |= ei[2 * EE - 1];
        g_is64 = (acc == 0u) ? 1 : 0;
    }
    int stride = gridDim.x * blockDim.x;
    for (int j = i; j < NN; j += stride) g_deg[j] = 0;
    if (i < DOUT) { g_sum[i] = 0.f; g_sqsum[i] = 0.f; }
}

// ---------------- CSR build ---------------------------------------------------
__global__ __launch_bounds__(256) void k_hist(const void* __restrict__ eiv) {
    int e = blockIdx.x * blockDim.x + threadIdx.x;
    if (e >= EE) return;
    atomicAdd(&g_deg[load_dst(eiv, e)], 1);
}

__global__ __launch_bounds__(SCAN_BLK) void k_scan1() {
    __shared__ int s[SCAN_BLK];
    int i = blockIdx.x * SCAN_BLK + threadIdx.x;
    int v = (i < NN) ? g_deg[i] : 0;
    s[threadIdx.x] = v;
    __syncthreads();
    for (int off = 1; off < SCAN_BLK; off <<= 1) {
        int t = (threadIdx.x >= off) ? s[threadIdx.x - off] : 0;
        __syncthreads();
        s[threadIdx.x] += t;
        __syncthreads();
    }
    if (i < NN) g_excl[i] = s[threadIdx.x] - v;
    if (threadIdx.x == SCAN_BLK - 1) g_bsum[blockIdx.x] = s[SCAN_BLK - 1];
}

// warp-parallel exclusive scan over NBLK (<=64) block sums
__global__ void k_scan2() {
    int lane = threadIdx.x;
    int v0 = (lane < NBLK) ? g_bsum[lane] : 0;                 // 0..31
    int v1 = (32 + lane < NBLK) ? g_bsum[32 + lane] : 0;       // 32..63
    int s0 = v0, s1 = v1;
    #pragma unroll
    for (int off = 1; off < 32; off <<= 1) {
        int t0 = __shfl_up_sync(0xffffffffu, s0, off);
        int t1 = __shfl_up_sync(0xffffffffu, s1, off);
        if (lane >= off) { s0 += t0; s1 += t1; }
    }
    int tot0 = __shfl_sync(0xffffffffu, s0, 31);
    if (lane < NBLK) g_bsum[lane] = s0 - v0;
    if (32 + lane < NBLK) g_bsum[32 + lane] = tot0 + s1 - v1;
}

__global__ void k_scan3() {
    int i = blockIdx.x * blockDim.x + threadIdx.x;
    if (i >= NN) return;
    int o = g_excl[i] + g_bsum[i / SCAN_BLK];
    g_off[i] = o;
    g_cur[i] = o;
}

__global__ __launch_bounds__(256) void k_fill(const void* __restrict__ eiv) {
    int e = blockIdx.x * blockDim.x + threadIdx.x;
    if (e >= EE) return;
    int d = load_dst(eiv, e);
    int pos = atomicAdd(&g_cur[d], 1);
    g_csr[pos] = load_src(eiv, e);
}

// ---------------- gather: warp per node, writes MEAN into g_agg ---------------
__global__ __launch_bounds__(256) void k_gather(const float* __restrict__ x) {
    int node = (int)((blockIdx.x * blockDim.x + threadIdx.x) >> 5);
    int lane = threadIdx.x & 31;
    if (node >= NN) return;
    int start = g_off[node];
    int deg = g_deg[node];
    float4 acc = make_float4(0.f, 0.f, 0.f, 0.f);
    int j = 0;
    for (; j + 4 <= deg; j += 4) {
        int s0 = g_csr[start + j], s1 = g_csr[start + j + 1];
        int s2 = g_csr[start + j + 2], s3 = g_csr[start + j + 3];
        float4 v0 = __ldg((const float4*)x + (size_t)s0 * 32 + lane);
        float4 v1 = __ldg((const float4*)x + (size_t)s1 * 32 + lane);
        float4 v2 = __ldg((const float4*)x + (size_t)s2 * 32 + lane);
        float4 v3 = __ldg((const float4*)x + (size_t)s3 * 32 + lane);
        acc.x += v0.x + v1.x + v2.x + v3.x;
        acc.y += v0.y + v1.y + v2.y + v3.y;
        acc.z += v0.z + v1.z + v2.z + v3.z;
        acc.w += v0.w + v1.w + v2.w + v3.w;
    }
    for (; j < deg; j++) {
        int s = g_csr[start + j];
        float4 v = __ldg((const float4*)x + (size_t)s * 32 + lane);
        acc.x += v.x; acc.y += v.y; acc.z += v.z; acc.w += v.w;
    }
    float inv = 1.0f / fmaxf((float)deg, 1.0f);
    acc.x *= inv; acc.y *= inv; acc.z *= inv; acc.w *= inv;
    ((float4*)g_agg)[(size_t)node * 32 + lane] = acc;
}

// ---------------- kernel 1: pre = agg@Wl^T + x@Wr^T + fused BN stats ---------
// 128x128 tile per block, grid (NTILES, 2). 2 chains: rna(agg)*Wl, rna(x)*Wr.
__global__ __launch_bounds__(256, 2) void k_mma_pre(
    const float* __restrict__ xg, const float* __restrict__ Wl,
    const float* __restrict__ Wr)
{
    extern __shared__ float smf[];
    uint32_t sbase = (uint32_t)__cvta_generic_to_shared(smf);

    const int tid = threadIdx.x;
    const int warp = tid >> 5, lane = tid & 31;
    const int wm = warp >> 2, wn = warp & 3;          // 2 x 4 warp grid (64x32 warp tile)
    const int g_ = lane >> 2, t_ = lane & 3;
    const int row0 = blockIdx.x * MTILE;
    const int col0 = blockIdx.y * 128;

    auto load_stage = [&](int stg, int kc) {
        uint32_t sb = sbase + stg * (STAGE_F * 4);
        #pragma unroll
        for (int j = 0; j < 8; j++) {
            int i = tid + 256 * j;
            int part = i & 3;
            int r = (i >> 2) & 127;
            const float* src;
            uint32_t doff;
            if (j < 2)      { int gr = min(row0 + r, NN - 1);
                              src = g_agg + (size_t)gr * DIN;          doff = AG_OFF + r * SROW; }
            else if (j < 4) { int gr = min(row0 + r, NN - 1);
                              src = xg + (size_t)gr * DIN;             doff = X_OFF + r * SROW; }
            else if (j < 6) { src = Wl + (size_t)(col0 + r) * DIN;     doff = WL_OFF + r * SROW; }
            else            { src = Wr + (size_t)(col0 + r) * DIN;     doff = WR_OFF + r * SROW; }
            cp16(sb + (doff + part * 4) * 4, src + kc + part * 4);
        }
    };

    float acc[4][4][4];
    #pragma unroll
    for (int mt = 0; mt < 4; mt++)
        #pragma unroll
        for (int nt = 0; nt < 4; nt++)
            #pragma unroll
            for (int q = 0; q < 4; q++) acc[mt][nt][q] = 0.f;

    load_stage(0, 0);
    CP_COMMIT();

    for (int c = 0; c < 8; c++) {
        if (c < 7) { load_stage((c + 1) & 1, (c + 1) * 16); CP_COMMIT(); CP_WAIT1(); }
        else       { CP_WAIT0(); }
        __syncthreads();
        const float* st = smf + (c & 1) * STAGE_F;

        #pragma unroll
        for (int ks = 0; ks < 2; ks++) {
            const int kk = ks * 8 + t_;
            float blx[4], bly[4], brx[4], bry[4];
            #pragma unroll
            for (int nt = 0; nt < 4; nt++) {
                int n = wn * 32 + nt * 8 + g_;
                const float* B1 = st + WL_OFF + n * SROW;
                blx[nt] = to_tf32(B1[kk]); bly[nt] = to_tf32(B1[kk + 4]);
                const float* B2 = st + WR_OFF + n * SROW;
                brx[nt] = to_tf32(B2[kk]); bry[nt] = to_tf32(B2[kk + 4]);
            }
            #pragma unroll
            for (int mt = 0; mt < 4; mt++) {
                int r = wm * 64 + mt * 16 + g_;
                const float* A = st + AG_OFF + r * SROW;
                float a0 = to_tf32(A[kk]);
                float a1 = to_tf32(A[8 * SROW + kk]);
                float a2 = to_tf32(A[kk + 4]);
                float a3 = to_tf32(A[8 * SROW + kk + 4]);
                const float* X = st + X_OFF + r * SROW;
                float x0 = to_tf32(X[kk]);
                float x1 = to_tf32(X[8 * SROW + kk]);
                float x2 = to_tf32(X[kk + 4]);
                float x3 = to_tf32(X[8 * SROW + kk + 4]);
                #pragma unroll
                for (int nt = 0; nt < 4; nt++) {
                    MMA_TF32(acc[mt][nt], a0, a1, a2, a3, blx[nt], bly[nt]);
                    MMA_TF32(acc[mt][nt], x0, x1, x2, x3, brx[nt], bry[nt]);
                }
            }
        }
        __syncthreads();
    }

    // ---- epilogue: store g_pre + fused BN column stats ----
    float ps[8], pq[8];
    #pragma unroll
    for (int k = 0; k < 8; k++) { ps[k] = 0.f; pq[k] = 0.f; }

    #pragma unroll
    for (int mt = 0; mt < 4; mt++) {
        int ra = row0 + wm * 64 + mt * 16 + g_;
        int rb = ra + 8;
        bool va = ra < NN, vb = rb < NN;
        #pragma unroll
        for (int nt = 0; nt < 4; nt++) {
            int col = col0 + wn * 32 + nt * 8 + 2 * t_;
            if (va) {
                *(float2*)&g_pre[(size_t)ra * DOUT + col] =
                    make_float2(acc[mt][nt][0], acc[mt][nt][1]);
                ps[2 * nt]     += acc[mt][nt][0];
                ps[2 * nt + 1] += acc[mt][nt][1];
                pq[2 * nt]     += acc[mt][nt][0] * acc[mt][nt][0];
                pq[2 * nt + 1] += acc[mt][nt][1] * acc[mt][nt][1];
            }
            if (vb) {
                *(float2*)&g_pre[(size_t)rb * DOUT + col] =
                    make_float2(acc[mt][nt][2], acc[mt][nt][3]);
                ps[2 * nt]     += acc[mt][nt][2];
                ps[2 * nt + 1] += acc[mt][nt][3];
                pq[2 * nt]     += acc[mt][nt][2] * acc[mt][nt][2];
                pq[2 * nt + 1] += acc[mt][nt][3] * acc[mt][nt][3];
            }
        }
    }
    #pragma unroll
    for (int k = 0; k < 8; k++) {
        #pragma unroll
        for (int m = 4; m <= 16; m <<= 1) {
            ps[k] += __shfl_xor_sync(0xffffffffu, ps[k], m);
            pq[k] += __shfl_xor_sync(0xffffffffu, pq[k], m);
        }
    }
    if (g_ == 0) {
        #pragma unroll
        for (int nt = 0; nt < 4; nt++) {
            int col = col0 + wn * 32 + nt * 8 + 2 * t_;
            atomicAdd(&g_sum[col],       ps[2 * nt]);
            atomicAdd(&g_sum[col + 1],   ps[2 * nt + 1]);
            atomicAdd(&g_sqsum[col],     pq[2 * nt]);
            atomicAdd(&g_sqsum[col + 1], pq[2 * nt + 1]);
        }
    }
}

// ---------------- BN stats finalize -------------------------------------------
__global__ void k_stats(const float* __restrict__ gamma, const float* __restrict__ beta) {
    int j = threadIdx.x;
    const float invN = 1.0f / (float)NN;
    float mean = g_sum[j] * invN;
    float var = g_sqsum[j] * invN - mean * mean;
    float rstd = rsqrtf(var + BN_EPS);
    float sc = rstd * gamma[j];
    g_scale[j] = sc;
    g_shift[j] = beta[j] - mean * sc;
}

// ---------------- kernel 2: id = x@Wres^T, fused BN/ReLU/add -----------------
__global__ __launch_bounds__(256, 2) void k_mma_fin(
    const float* __restrict__ xg, const float* __restrict__ Wres,
    const float* __restrict__ bres, float* __restrict__ out)
{
    extern __shared__ float smf[];
    __shared__ float sSc[128], sSh[128], sBr[128];
    uint32_t sbase = (uint32_t)__cvta_generic_to_shared(smf);

    const int tid = threadIdx.x;
    const int warp = tid >> 5, lane = tid & 31;
    const int wm = warp >> 2, wn = warp & 3;
    const int g_ = lane >> 2, t_ = lane & 3;
    const int row0 = blockIdx.x * MTILE;
    const int col0 = blockIdx.y * 128;

    if (tid < 128) {
        sSc[tid] = g_scale[col0 + tid];
        sSh[tid] = g_shift[col0 + tid];
        sBr[tid] = __ldg(&bres[col0 + tid]);
    }

    auto load_stage = [&](int stg, int kc) {
        uint32_t sb = sbase + stg * (STAGE2_F * 4);
        #pragma unroll
        for (int j = 0; j < 4; j++) {
            int i = tid + 256 * j;
            int part = i & 3;
            int r = (i >> 2) & 127;
            const float* src;
            uint32_t doff;
            if (j < 2) { int gr = min(row0 + r, NN - 1);
                         src = xg + (size_t)gr * DIN;             doff = X2_OFF + r * SROW; }
            else       { src = Wres + (size_t)(col0 + r) * DIN;   doff = W2_OFF + r * SROW; }
            cp16(sb + (doff + part * 4) * 4, src + kc + part * 4);
        }
    };

    float acc[4][4][4];
    #pragma unroll
    for (int mt = 0; mt < 4; mt++)
        #pragma unroll
        for (int nt = 0; nt < 4; nt++)
            #pragma unroll
            for (int q = 0; q < 4; q++) acc[mt][nt][q] = 0.f;

    load_stage(0, 0);
    CP_COMMIT();

    for (int c = 0; c < 8; c++) {
        if (c < 7) { load_stage((c + 1) & 1, (c + 1) * 16); CP_COMMIT(); CP_WAIT1(); }
        else       { CP_WAIT0(); }
        __syncthreads();
        const float* st = smf + (c & 1) * STAGE2_F;

        #pragma unroll
        for (int ks = 0; ks < 2; ks++) {
            const int kk = ks * 8 + t_;
            float bx[4], by[4];
            #pragma unroll
            for (int nt = 0; nt < 4; nt++) {
                int n = wn * 32 + nt * 8 + g_;
                const float* B = st + W2_OFF + n * SROW;
                bx[nt] = to_tf32(B[kk]); by[nt] = to_tf32(B[kk + 4]);
            }
            #pragma unroll
            for (int mt = 0; mt < 4; mt++) {
                int r = wm * 64 + mt * 16 + g_;
                const float* X = st + X2_OFF + r * SROW;
                float x0 = to_tf32(X[kk]);
                float x1 = to_tf32(X[8 * SROW + kk]);
                float x2 = to_tf32(X[kk + 4]);
                float x3 = to_tf32(X[8 * SROW + kk + 4]);
                #pragma unroll
                for (int nt = 0; nt < 4; nt++)
                    MMA_TF32(acc[mt][nt], x0, x1, x2, x3, bx[nt], by[nt]);
            }
        }
        __syncthreads();
    }

    // ---- fused epilogue: out = relu(pre*sc+sh) + acc + bres ----
    #pragma unroll
    for (int mt = 0; mt < 4; mt++) {
        int ra = row0 + wm * 64 + mt * 16 + g_;
        int rb = ra + 8;
        #pragma unroll
        for (int nt = 0; nt < 4; nt++) {
            int lcol = wn * 32 + nt * 8 + 2 * t_;
            int col = col0 + lcol;
            float sc0 = sSc[lcol], sc1 = sSc[lcol + 1];
            float sh0 = sSh[lcol], sh1 = sSh[lcol + 1];
            float br0 = sBr[lcol], br1 = sBr[lcol + 1];
            if (ra < NN) {
                float2 pv = *(const float2*)&g_pre[(size_t)ra * DOUT + col];
                float2 o;
                o.x = fmaxf(pv.x * sc0 + sh0, 0.f) + acc[mt][nt][0] + br0;
                o.y = fmaxf(pv.y * sc1 + sh1, 0.f) + acc[mt][nt][1] + br1;
                *(float2*)&out[(size_t)ra * DOUT + col] = o;
            }
            if (rb < NN) {
                float2 pv = *(const float2*)&g_pre[(size_t)rb * DOUT + col];
                float2 o;
                o.x = fmaxf(pv.x * sc0 + sh0, 0.f) + acc[mt][nt][2] + br0;
                o.y = fmaxf(pv.y * sc1 + sh1, 0.f) + acc[mt][nt][3] + br1;
                *(float2*)&out[(size_t)rb * DOUT + col] = o;
            }
        }
    }
}

// ---------------- launch ------------------------------------------------------
extern "C" void kernel_launch(void* const* d_in, const int* in_sizes, int n_in,
                              void* d_out, int out_size) {
    const float* x     = (const float*)d_in[0];
    const void*  ei    = d_in[1];
    const float* Wl    = (const float*)d_in[2];
    // d_in[3] = b_l — absorbed by BatchNorm, unused
    const float* Wr    = (const float*)d_in[4];
    const float* Wres  = (const float*)d_in[5];
    const float* bres  = (const float*)d_in[6];
    const float* gamma = (const float*)d_in[7];
    const float* beta  = (const float*)d_in[8];
    float* out = (float*)d_out;

    cudaFuncSetAttribute(k_mma_pre, cudaFuncAttributeMaxDynamicSharedMemorySize, SM1_BYTES);
    cudaFuncSetAttribute(k_mma_fin, cudaFuncAttributeMaxDynamicSharedMemorySize, SM2_BYTES);

    k_init<<<64, 1024>>>((const unsigned*)ei);
    k_hist<<<(EE + 255) / 256, 256>>>(ei);
    k_scan1<<<NBLK, SCAN_BLK>>>();
    k_scan2<<<1, 32>>>();
    k_scan3<<<(NN + 255) / 256, 256>>>();
    k_fill<<<(EE + 255) / 256, 256>>>(ei);
    k_gather<<<(NN * 32 + 255) / 256, 256>>>(x);
    dim3 g1(NTILES, 2);
    k_mma_pre<<<g1, 256, SM1_BYTES>>>(x, Wl, Wr);
    k_stats<<<1, DOUT>>>(gamma, beta);
    k_mma_fin<<<g1, 256, SM2_BYTES>>>(x, Wres, bres, out);
}

// round 12
// speedup vs baseline: 2.5123x; 1.0767x over previous
#include <cuda_runtime.h>
#include <cstdint>

#define NN   50000
#define EE   640000
#define DIN  128
#define DOUT 256
#define BN_EPS 1e-5f
#define MTILE 128
#define NTILES ((NN + MTILE - 1) / MTILE)   // 391
#define SROW 20                              // row stride in floats
#define SCAN_BLK 1024
#define NBLK ((NN + SCAN_BLK - 1) / SCAN_BLK)   // 49

// ---- kernel1 stage layout (floats): 4 tiles of 128 rows x 16 k ----
#define AG_OFF 0
#define X_OFF  (128 * SROW)
#define WL_OFF (2 * 128 * SROW)
#define WR_OFF (3 * 128 * SROW)
#define STAGE_F (4 * 128 * SROW)            // 10240 floats
#define SM1_BYTES (2 * STAGE_F * 4)         // 81920 B

// ---- kernel2 stage layout ----
#define X2_OFF 0
#define W2_OFF (128 * SROW)
#define STAGE2_F (2 * 128 * SROW)           // 5120 floats
#define SM2_BYTES (2 * STAGE2_F * 4)        // 40960 B

// ---------------- scratch (static __device__, no allocation) ----------------
__device__ __align__(16) float g_agg[(size_t)NN * DIN];   // 25.6 MB (stores MEAN)
__device__ __align__(16) float g_pre[(size_t)NN * DOUT];  // 51.2 MB
__device__ int   g_deg[NN];
__device__ int   g_excl[NN];
__device__ int   g_off[NN];
__device__ int   g_cur[NN];
__device__ int   g_bsum[NBLK];
__device__ int   g_csr[EE];
__device__ float g_sum[DOUT];
__device__ float g_sqsum[DOUT];
__device__ float g_scale[DOUT];
__device__ float g_shift[DOUT];
__device__ int   g_is64;

// ---------------- helpers -----------------------------------------------------
__device__ __forceinline__ float to_tf32(float v) {
    uint32_t o;
    asm("cvt.rna.tf32.f32 %0, %1;" : "=r"(o) : "f"(v));
    return __uint_as_float(o);
}
__device__ __forceinline__ void cp16(uint32_t dst, const float* src) {
    asm volatile("cp.async.cg.shared.global [%0], [%1], 16;" :: "r"(dst), "l"(src));
}
#define CP_COMMIT() asm volatile("cp.async.commit_group;" ::: "memory")
#define CP_WAIT1()  asm volatile("cp.async.wait_group 1;" ::: "memory")
#define CP_WAIT0()  asm volatile("cp.async.wait_group 0;" ::: "memory")

#define MMA_TF32(c, A0, A1, A2, A3, B0, B1)                                  \
    asm volatile(                                                            \
        "mma.sync.aligned.m16n8k8.row.col.f32.tf32.tf32.f32 "                \
        "{%0,%1,%2,%3}, {%4,%5,%6,%7}, {%8,%9}, {%0,%1,%2,%3};"              \
        : "+f"((c)[0]), "+f"((c)[1]), "+f"((c)[2]), "+f"((c)[3])             \
        : "r"(__float_as_uint(A0)), "r"(__float_as_uint(A1)),                \
          "r"(__float_as_uint(A2)), "r"(__float_as_uint(A3)),                \
          "r"(__float_as_uint(B0)), "r"(__float_as_uint(B1)))

__device__ __forceinline__ int load_dst(const void* eiv, int e) {
    return g_is64 ? (int)((const long long*)eiv)[EE + e] : ((const int*)eiv)[EE + e];
}
__device__ __forceinline__ int load_src(const void* eiv, int e) {
    return g_is64 ? (int)((const long long*)eiv)[e] : ((const int*)eiv)[e];
}

// ---------------- init: dtype detect + zero small arrays ---------------------
__global__ void k_init(const unsigned* __restrict__ ei) {
    int i = blockIdx.x * blockDim.x + threadIdx.x;
    if (i == 0) {
        unsigned acc = 0;
        #pragma unroll
        for (int k = 0; k < 8; k++) acc |= ei[2 * k + 1];
        acc |= ei[2 * EE - 1];
        g_is64 = (acc == 0u) ? 1 : 0;
    }
    int stride = gridDim.x * blockDim.x;
    for (int j = i; j < NN; j += stride) g_deg[j] = 0;
    if (i < DOUT) { g_sum[i] = 0.f; g_sqsum[i] = 0.f; }
}

// ---------------- CSR build ---------------------------------------------------
__global__ __launch_bounds__(256) void k_hist(const void* __restrict__ eiv) {
    int e = blockIdx.x * blockDim.x + threadIdx.x;
    if (e >= EE) return;
    atomicAdd(&g_deg[load_dst(eiv, e)], 1);
}

__global__ __launch_bounds__(SCAN_BLK) void k_scan1() {
    __shared__ int s[SCAN_BLK];
    int i = blockIdx.x * SCAN_BLK + threadIdx.x;
    int v = (i < NN) ? g_deg[i] : 0;
    s[threadIdx.x] = v;
    __syncthreads();
    for (int off = 1; off < SCAN_BLK; off <<= 1) {
        int t = (threadIdx.x >= off) ? s[threadIdx.x - off] : 0;
        __syncthreads();
        s[threadIdx.x] += t;
        __syncthreads();
    }
    if (i < NN) g_excl[i] = s[threadIdx.x] - v;
    if (threadIdx.x == SCAN_BLK - 1) g_bsum[blockIdx.x] = s[SCAN_BLK - 1];
}

// scan3 with inlined scan-of-block-sums (every block redundantly scans 49 ints)
__global__ __launch_bounds__(256) void k_scan3() {
    __shared__ int sOff[64];
    int t = threadIdx.x;
    if (t < 32) {
        int v0 = (t < NBLK) ? g_bsum[t] : 0;
        int v1 = (32 + t < NBLK) ? g_bsum[32 + t] : 0;
        int s0 = v0, s1 = v1;
        #pragma unroll
        for (int off = 1; off < 32; off <<= 1) {
            int t0 = __shfl_up_sync(0xffffffffu, s0, off);
            int t1 = __shfl_up_sync(0xffffffffu, s1, off);
            if (t >= off) { s0 += t0; s1 += t1; }
        }
        int tot0 = __shfl_sync(0xffffffffu, s0, 31);
        sOff[t] = s0 - v0;
        sOff[32 + t] = tot0 + s1 - v1;
    }
    __syncthreads();
    int i = blockIdx.x * blockDim.x + threadIdx.x;
    if (i >= NN) return;
    int o = g_excl[i] + sOff[i / SCAN_BLK];
    g_off[i] = o;
    g_cur[i] = o;
}

__global__ __launch_bounds__(256) void k_fill(const void* __restrict__ eiv) {
    int e = blockIdx.x * blockDim.x + threadIdx.x;
    if (e >= EE) return;
    int d = load_dst(eiv, e);
    int pos = atomicAdd(&g_cur[d], 1);
    g_csr[pos] = load_src(eiv, e);
}

// ---------------- gather: warp per node, writes MEAN into g_agg ---------------
__global__ __launch_bounds__(256) void k_gather(const float* __restrict__ x) {
    int node = (int)((blockIdx.x * blockDim.x + threadIdx.x) >> 5);
    int lane = threadIdx.x & 31;
    if (node >= NN) return;
    int start = g_off[node];
    int deg = g_deg[node];
    float4 acc = make_float4(0.f, 0.f, 0.f, 0.f);
    int j = 0;
    for (; j + 4 <= deg; j += 4) {
        int s0 = g_csr[start + j], s1 = g_csr[start + j + 1];
        int s2 = g_csr[start + j + 2], s3 = g_csr[start + j + 3];
        float4 v0 = __ldg((const float4*)x + (size_t)s0 * 32 + lane);
        float4 v1 = __ldg((const float4*)x + (size_t)s1 * 32 + lane);
        float4 v2 = __ldg((const float4*)x + (size_t)s2 * 32 + lane);
        float4 v3 = __ldg((const float4*)x + (size_t)s3 * 32 + lane);
        acc.x += v0.x + v1.x + v2.x + v3.x;
        acc.y += v0.y + v1.y + v2.y + v3.y;
        acc.z += v0.z + v1.z + v2.z + v3.z;
        acc.w += v0.w + v1.w + v2.w + v3.w;
    }
    for (; j < deg; j++) {
        int s = g_csr[start + j];
        float4 v = __ldg((const float4*)x + (size_t)s * 32 + lane);
        acc.x += v.x; acc.y += v.y; acc.z += v.z; acc.w += v.w;
    }
    float inv = 1.0f / fmaxf((float)deg, 1.0f);
    acc.x *= inv; acc.y *= inv; acc.z *= inv; acc.w *= inv;
    ((float4*)g_agg)[(size_t)node * 32 + lane] = acc;
}

// ---------------- kernel 1: pre = agg@Wl^T + x@Wr^T + fused BN stats ---------
__global__ __launch_bounds__(256, 2) void k_mma_pre(
    const float* __restrict__ xg, const float* __restrict__ Wl,
    const float* __restrict__ Wr)
{
    extern __shared__ float smf[];
    uint32_t sbase = (uint32_t)__cvta_generic_to_shared(smf);

    const int tid = threadIdx.x;
    const int warp = tid >> 5, lane = tid & 31;
    const int wm = warp >> 2, wn = warp & 3;
    const int g_ = lane >> 2, t_ = lane & 3;
    const int row0 = blockIdx.x * MTILE;
    const int col0 = blockIdx.y * 128;

    auto load_stage = [&](int stg, int kc) {
        uint32_t sb = sbase + stg * (STAGE_F * 4);
        #pragma unroll
        for (int j = 0; j < 8; j++) {
            int i = tid + 256 * j;
            int part = i & 3;
            int r = (i >> 2) & 127;
            const float* src;
            uint32_t doff;
            if (j < 2)      { int gr = min(row0 + r, NN - 1);
                              src = g_agg + (size_t)gr * DIN;          doff = AG_OFF + r * SROW; }
            else if (j < 4) { int gr = min(row0 + r, NN - 1);
                              src = xg + (size_t)gr * DIN;             doff = X_OFF + r * SROW; }
            else if (j < 6) { src = Wl + (size_t)(col0 + r) * DIN;     doff = WL_OFF + r * SROW; }
            else            { src = Wr + (size_t)(col0 + r) * DIN;     doff = WR_OFF + r * SROW; }
            cp16(sb + (doff + part * 4) * 4, src + kc + part * 4);
        }
    };

    float acc[4][4][4];
    #pragma unroll
    for (int mt = 0; mt < 4; mt++)
        #pragma unroll
        for (int nt = 0; nt < 4; nt++)
            #pragma unroll
            for (int q = 0; q < 4; q++) acc[mt][nt][q] = 0.f;

    load_stage(0, 0);
    CP_COMMIT();

    for (int c = 0; c < 8; c++) {
        if (c < 7) { load_stage((c + 1) & 1, (c + 1) * 16); CP_COMMIT(); CP_WAIT1(); }
        else       { CP_WAIT0(); }
        __syncthreads();
        const float* st = smf + (c & 1) * STAGE_F;

        #pragma unroll
        for (int ks = 0; ks < 2; ks++) {
            const int kk = ks * 8 + t_;
            float blx[4], bly[4], brx[4], bry[4];
            #pragma unroll
            for (int nt = 0; nt < 4; nt++) {
                int n = wn * 32 + nt * 8 + g_;
                const float* B1 = st + WL_OFF + n * SROW;
                blx[nt] = to_tf32(B1[kk]); bly[nt] = to_tf32(B1[kk + 4]);
                const float* B2 = st + WR_OFF + n * SROW;
                brx[nt] = to_tf32(B2[kk]); bry[nt] = to_tf32(B2[kk + 4]);
            }
            #pragma unroll
            for (int mt = 0; mt < 4; mt++) {
                int r = wm * 64 + mt * 16 + g_;
                const float* A = st + AG_OFF + r * SROW;
                float a0 = to_tf32(A[kk]);
                float a1 = to_tf32(A[8 * SROW + kk]);
                float a2 = to_tf32(A[kk + 4]);
                float a3 = to_tf32(A[8 * SROW + kk + 4]);
                const float* X = st + X_OFF + r * SROW;
                float x0 = to_tf32(X[kk]);
                float x1 = to_tf32(X[8 * SROW + kk]);
                float x2 = to_tf32(X[kk + 4]);
                float x3 = to_tf32(X[8 * SROW + kk + 4]);
                #pragma unroll
                for (int nt = 0; nt < 4; nt++) {
                    MMA_TF32(acc[mt][nt], a0, a1, a2, a3, blx[nt], bly[nt]);
                    MMA_TF32(acc[mt][nt], x0, x1, x2, x3, brx[nt], bry[nt]);
                }
            }
        }
        __syncthreads();
    }

    // ---- epilogue: store g_pre + fused BN column stats ----
    float ps[8], pq[8];
    #pragma unroll
    for (int k = 0; k < 8; k++) { ps[k] = 0.f; pq[k] = 0.f; }

    #pragma unroll
    for (int mt = 0; mt < 4; mt++) {
        int ra = row0 + wm * 64 + mt * 16 + g_;
        int rb = ra + 8;
        bool va = ra < NN, vb = rb < NN;
        #pragma unroll
        for (int nt = 0; nt < 4; nt++) {
            int col = col0 + wn * 32 + nt * 8 + 2 * t_;
            if (va) {
                *(float2*)&g_pre[(size_t)ra * DOUT + col] =
                    make_float2(acc[mt][nt][0], acc[mt][nt][1]);
                ps[2 * nt]     += acc[mt][nt][0];
                ps[2 * nt + 1] += acc[mt][nt][1];
                pq[2 * nt]     += acc[mt][nt][0] * acc[mt][nt][0];
                pq[2 * nt + 1] += acc[mt][nt][1] * acc[mt][nt][1];
            }
            if (vb) {
                *(float2*)&g_pre[(size_t)rb * DOUT + col] =
                    make_float2(acc[mt][nt][2], acc[mt][nt][3]);
                ps[2 * nt]     += acc[mt][nt][2];
                ps[2 * nt + 1] += acc[mt][nt][3];
                pq[2 * nt]     += acc[mt][nt][2] * acc[mt][nt][2];
                pq[2 * nt + 1] += acc[mt][nt][3] * acc[mt][nt][3];
            }
        }
    }
    #pragma unroll
    for (int k = 0; k < 8; k++) {
        #pragma unroll
        for (int m = 4; m <= 16; m <<= 1) {
            ps[k] += __shfl_xor_sync(0xffffffffu, ps[k], m);
            pq[k] += __shfl_xor_sync(0xffffffffu, pq[k], m);
        }
    }
    if (g_ == 0) {
        #pragma unroll
        for (int nt = 0; nt < 4; nt++) {
            int col = col0 + wn * 32 + nt * 8 + 2 * t_;
            atomicAdd(&g_sum[col],       ps[2 * nt]);
            atomicAdd(&g_sum[col + 1],   ps[2 * nt + 1]);
            atomicAdd(&g_sqsum[col],     pq[2 * nt]);
            atomicAdd(&g_sqsum[col + 1], pq[2 * nt + 1]);
        }
    }
}

// ---------------- BN stats finalize -------------------------------------------
__global__ void k_stats(const float* __restrict__ gamma, const float* __restrict__ beta) {
    int j = threadIdx.x;
    const float invN = 1.0f / (float)NN;
    float mean = g_sum[j] * invN;
    float var = g_sqsum[j] * invN - mean * mean;
    float rstd = rsqrtf(var + BN_EPS);
    float sc = rstd * gamma[j];
    g_scale[j] = sc;
    g_shift[j] = beta[j] - mean * sc;
}

// ---------------- kernel 2: id = x@Wres^T + bres -> out (no BN dependency) ---
__global__ __launch_bounds__(256, 2) void k_mma_id(
    const float* __restrict__ xg, const float* __restrict__ Wres,
    const float* __restrict__ bres, float* __restrict__ out)
{
    extern __shared__ float smf[];
    __shared__ float sBr[128];
    uint32_t sbase = (uint32_t)__cvta_generic_to_shared(smf);

    const int tid = threadIdx.x;
    const int warp = tid >> 5, lane = tid & 31;
    const int wm = warp >> 2, wn = warp & 3;
    const int g_ = lane >> 2, t_ = lane & 3;
    const int row0 = blockIdx.x * MTILE;
    const int col0 = blockIdx.y * 128;

    if (tid < 128) sBr[tid] = __ldg(&bres[col0 + tid]);

    auto load_stage = [&](int stg, int kc) {
        uint32_t sb = sbase + stg * (STAGE2_F * 4);
        #pragma unroll
        for (int j = 0; j < 4; j++) {
            int i = tid + 256 * j;
            int part = i & 3;
            int r = (i >> 2) & 127;
            const float* src;
            uint32_t doff;
            if (j < 2) { int gr = min(row0 + r, NN - 1);
                         src = xg + (size_t)gr * DIN;             doff = X2_OFF + r * SROW; }
            else       { src = Wres + (size_t)(col0 + r) * DIN;   doff = W2_OFF + r * SROW; }
            cp16(sb + (doff + part * 4) * 4, src + kc + part * 4);
        }
    };

    float acc[4][4][4];
    #pragma unroll
    for (int mt = 0; mt < 4; mt++)
        #pragma unroll
        for (int nt = 0; nt < 4; nt++)
            #pragma unroll
            for (int q = 0; q < 4; q++) acc[mt][nt][q] = 0.f;

    load_stage(0, 0);
    CP_COMMIT();

    for (int c = 0; c < 8; c++) {
        if (c < 7) { load_stage((c + 1) & 1, (c + 1) * 16); CP_COMMIT(); CP_WAIT1(); }
        else       { CP_WAIT0(); }
        __syncthreads();
        const float* st = smf + (c & 1) * STAGE2_F;

        #pragma unroll
        for (int ks = 0; ks < 2; ks++) {
            const int kk = ks * 8 + t_;
            float bx[4], by[4];
            #pragma unroll
            for (int nt = 0; nt < 4; nt++) {
                int n = wn * 32 + nt * 8 + g_;
                const float* B = st + W2_OFF + n * SROW;
                bx[nt] = to_tf32(B[kk]); by[nt] = to_tf32(B[kk + 4]);
            }
            #pragma unroll
            for (int mt = 0; mt < 4; mt++) {
                int r = wm * 64 + mt * 16 + g_;
                const float* X = st + X2_OFF + r * SROW;
                float x0 = to_tf32(X[kk]);
                float x1 = to_tf32(X[8 * SROW + kk]);
                float x2 = to_tf32(X[kk + 4]);
                float x3 = to_tf32(X[8 * SROW + kk + 4]);
                #pragma unroll
                for (int nt = 0; nt < 4; nt++)
                    MMA_TF32(acc[mt][nt], x0, x1, x2, x3, bx[nt], by[nt]);
            }
        }
        __syncthreads();
    }

    #pragma unroll
    for (int mt = 0; mt < 4; mt++) {
        int ra = row0 + wm * 64 + mt * 16 + g_;
        int rb = ra + 8;
        #pragma unroll
        for (int nt = 0; nt < 4; nt++) {
            int lcol = wn * 32 + nt * 8 + 2 * t_;
            int col = col0 + lcol;
            float br0 = sBr[lcol], br1 = sBr[lcol + 1];
            if (ra < NN)
                *(float2*)&out[(size_t)ra * DOUT + col] =
                    make_float2(acc[mt][nt][0] + br0, acc[mt][nt][1] + br1);
            if (rb < NN)
                *(float2*)&out[(size_t)rb * DOUT + col] =
                    make_float2(acc[mt][nt][2] + br0, acc[mt][nt][3] + br1);
        }
    }
}

// ---------------- combine: out = relu(pre*sc+sh) + out ------------------------
__global__ __launch_bounds__(256) void k_combine(float* __restrict__ out) {
    size_t i = (size_t)blockIdx.x * blockDim.x + threadIdx.x;
    size_t stride = (size_t)gridDim.x * blockDim.x;
    const size_t total = (size_t)NN * (DOUT / 4);
    const float4* pre4 = (const float4*)g_pre;
    float4* out4 = (float4*)out;
    for (size_t j = i; j < total; j += stride) {
        int col4 = (int)(j & 63) * 4;
        float4 pv = pre4[j];
        float4 ov = out4[j];
        float4 sc = *(const float4*)&g_scale[col4];
        float4 sh = *(const float4*)&g_shift[col4];
        float4 o;
        o.x = fmaxf(pv.x * sc.x + sh.x, 0.f) + ov.x;
        o.y = fmaxf(pv.y * sc.y + sh.y, 0.f) + ov.y;
        o.z = fmaxf(pv.z * sc.z + sh.z, 0.f) + ov.z;
        o.w = fmaxf(pv.w * sc.w + sh.w, 0.f) + ov.w;
        out4[j] = o;
    }
}

// ---------------- launch ------------------------------------------------------
extern "C" void kernel_launch(void* const* d_in, const int* in_sizes, int n_in,
                              void* d_out, int out_size) {
    const float* x     = (const float*)d_in[0];
    const void*  ei    = d_in[1];
    const float* Wl    = (const float*)d_in[2];
    // d_in[3] = b_l — absorbed by BatchNorm, unused
    const float* Wr    = (const float*)d_in[4];
    const float* Wres  = (const float*)d_in[5];
    const float* bres  = (const float*)d_in[6];
    const float* gamma = (const float*)d_in[7];
    const float* beta  = (const float*)d_in[8];
    float* out = (float*)d_out;

    cudaFuncSetAttribute(k_mma_pre, cudaFuncAttributeMaxDynamicSharedMemorySize, SM1_BYTES);
    cudaFuncSetAttribute(k_mma_id, cudaFuncAttributeMaxDynamicSharedMemorySize, SM2_BYTES);

    // second stream for the independent id-GEMM (graph-captured via event fork/join;
    // stream/event handles are host objects, intentionally not destroyed — capture-safe)
    cudaStream_t s2;
    cudaEvent_t ev_fork, ev_id;
    cudaStreamCreateWithFlags(&s2, cudaStreamNonBlocking);
    cudaEventCreateWithFlags(&ev_fork, cudaEventDisableTiming);
    cudaEventCreateWithFlags(&ev_id, cudaEventDisableTiming);

    dim3 g1(NTILES, 2);

    cudaEventRecord(ev_fork, 0);
    cudaStreamWaitEvent(s2, ev_fork, 0);
    k_mma_id<<<g1, 256, SM2_BYTES, s2>>>(x, Wres, bres, out);
    cudaEventRecord(ev_id, s2);

    k_init<<<64, 1024>>>((const unsigned*)ei);
    k_hist<<<(EE + 255) / 256, 256>>>(ei);
    k_scan1<<<NBLK, SCAN_BLK>>>();
    k_scan3<<<(NN + 255) / 256, 256>>>();
    k_fill<<<(EE + 255) / 256, 256>>>(ei);
    k_gather<<<(NN * 32 + 255) / 256, 256>>>(x);
    k_mma_pre<<<g1, 256, SM1_BYTES>>>(x, Wl, Wr);
    k_stats<<<1, DOUT>>>(gamma, beta);

    cudaStreamWaitEvent(0, ev_id, 0);
    k_combine<<<2048, 256>>>(out);
}